// round 1
// baseline (speedup 1.0000x reference)
#include <cuda_runtime.h>
#include <math.h>

// Problem constants
#define PB 8
#define PT 512
#define PD 1024
#define PH 16
#define PDH 64
#define PBH (PB * PH)

// Scratch (device globals: allocation-free)
__device__ float g_Q[PBH * PT * PDH];
__device__ float g_K[PBH * PT * PDH];
__device__ float g_V[PBH * PT * PDH];
__device__ float g_att[PB * PT * PD];

// ---------------- packed f32x2 helpers (sm_10x FFMA2) ----------------
__device__ __forceinline__ unsigned long long pack2(float x, float y) {
    unsigned long long r;
    asm("mov.b64 %0, {%1, %2};" : "=l"(r) : "f"(x), "f"(y));
    return r;
}
__device__ __forceinline__ void unpack2(unsigned long long v, float &x, float &y) {
    asm("mov.b64 {%0, %1}, %2;" : "=f"(x), "=f"(y) : "l"(v));
}
__device__ __forceinline__ void ffma2(unsigned long long &d,
                                      unsigned long long a,
                                      unsigned long long b) {
    asm("fma.rn.f32x2 %0, %1, %2, %0;" : "+l"(d) : "l"(a), "l"(b));
}
__device__ __forceinline__ unsigned long long fmul2(unsigned long long a,
                                                    unsigned long long b) {
    unsigned long long r;
    asm("mul.rn.f32x2 %0, %1, %2;" : "=l"(r) : "l"(a), "l"(b));
    return r;
}

// =====================================================================
// Kernel 1: per-head QKV projection.
//   grid = (T/64, B*H, 3), block = 256.
//   Each block: one 64x64 output tile of (Xh @ W[h]) + bias for Q/K/V.
// =====================================================================
__global__ __launch_bounds__(256) void qkv_kernel(
    const float* __restrict__ X,
    const float* __restrict__ Wq, const float* __restrict__ bq,
    const float* __restrict__ Wk, const float* __restrict__ bk,
    const float* __restrict__ Wv, const float* __restrict__ bv)
{
    __shared__ __align__(16) float Xs[64 * 65];  // [d][t] transposed
    __shared__ __align__(16) float Ws[64 * 64];  // [d][e]
    __shared__ __align__(16) float bs[64];

    const int tid   = threadIdx.x;
    const int ttile = blockIdx.x;
    const int bh    = blockIdx.y;
    const int which = blockIdx.z;
    const int b = bh / PH, h = bh % PH;

    const float* W; const float* bias; float* out;
    if (which == 0)      { W = Wq + h * PDH * PDH; bias = bq + h * PDH; out = g_Q; }
    else if (which == 1) { W = Wk + h * PDH * PDH; bias = bk + h * PDH; out = g_K; }
    else                 { W = Wv + h * PDH * PDH; bias = bv + h * PDH; out = g_V; }

    for (int i = tid; i < 4096; i += 256) Ws[i] = W[i];
    if (tid < 64) bs[tid] = bias[tid];
    const int t0 = ttile * 64;
    for (int i = tid; i < 4096; i += 256) {
        int t = i >> 6, d = i & 63;
        Xs[d * 65 + t] = X[(b * PT + t0 + t) * PD + h * PDH + d];
    }
    __syncthreads();

    const int m0 = (tid >> 4) << 2;   // 4 t-rows
    const int n1 = tid & 15;          // e pairs: {2n1,2n1+1} and +32
    unsigned long long acc[4][2];
    #pragma unroll
    for (int i = 0; i < 4; i++) { acc[i][0] = 0ull; acc[i][1] = 0ull; }

    #pragma unroll 4
    for (int d = 0; d < 64; d++) {
        unsigned long long B0 = *(const unsigned long long*)&Ws[d * 64 + 2 * n1];
        unsigned long long B1 = *(const unsigned long long*)&Ws[d * 64 + 2 * n1 + 32];
        #pragma unroll
        for (int i = 0; i < 4; i++) {
            float a = Xs[d * 65 + m0 + i];
            unsigned long long A = pack2(a, a);
            ffma2(acc[i][0], A, B0);
            ffma2(acc[i][1], A, B1);
        }
    }

    float2 bb0 = *(const float2*)&bs[2 * n1];
    float2 bb1 = *(const float2*)&bs[2 * n1 + 32];
    #pragma unroll
    for (int i = 0; i < 4; i++) {
        int row = bh * PT + t0 + m0 + i;
        float x, y;
        unpack2(acc[i][0], x, y);
        *(float2*)&out[row * PDH + 2 * n1] = make_float2(x + bb0.x, y + bb0.y);
        unpack2(acc[i][1], x, y);
        *(float2*)&out[row * PDH + 2 * n1 + 32] = make_float2(x + bb1.x, y + bb1.y);
    }
}

// =====================================================================
// Kernel 2: attention per (b,h, 64-query tile), online softmax over
// 16 key-tiles of 32.  grid = (T/64, B*H), block = 256.
// =====================================================================
__global__ __launch_bounds__(256) void attn_kernel(const int* __restrict__ mask)
{
    __shared__ __align__(16) float Qt[64 * 65];  // [d][q]
    __shared__ __align__(16) float Kt[64 * 34];  // [d][k] (32-wide, pad 34)
    __shared__ __align__(16) float Vs[32 * 64];  // [k][e]
    __shared__ __align__(16) float Ps[64 * 34];  // [q][k] probs
    __shared__ float m_s[64], l_s[64], c_s[64];
    __shared__ int   msk[32];

    const int tid   = threadIdx.x;
    const int qtile = blockIdx.x;
    const int bh    = blockIdx.y;
    const int b = bh / PH, h = bh % PH;
    const int qbase = qtile * 64;

    for (int i = tid; i < 4096; i += 256) {
        int q = i >> 6, d = i & 63;
        Qt[d * 65 + q] = g_Q[(bh * PT + qbase + q) * PDH + d];
    }
    if (tid < 64) { m_s[tid] = -INFINITY; l_s[tid] = 0.f; }

    const int q0 = (tid >> 4) << 2;   // 4 q-rows
    const int p1 = tid & 15;          // k-pair / e-pair base
    const float scale = 0.125f;       // 1/sqrt(64)

    unsigned long long o_acc[4][2];
    #pragma unroll
    for (int i = 0; i < 4; i++) { o_acc[i][0] = 0ull; o_acc[i][1] = 0ull; }

    for (int kt = 0; kt < 16; kt++) {
        __syncthreads();   // previous iter's Ps/Vs/Kt consumers done
        for (int i = tid; i < 2048; i += 256) {
            int k = i >> 6, d = i & 63;
            Kt[d * 34 + k] = g_K[(bh * PT + kt * 32 + k) * PDH + d];
        }
        for (int i = tid; i < 2048; i += 256) {
            int k = i >> 6, e = i & 63;
            Vs[k * 64 + e] = g_V[(bh * PT + kt * 32 + k) * PDH + e];
        }
        if (tid < 32) msk[tid] = mask[b * PT + kt * 32 + tid];
        __syncthreads();

        // ---- scores: 64q x 32k, thread = 4q x (k pair {2p1, 2p1+1}) ----
        unsigned long long s2[4];
        #pragma unroll
        for (int i = 0; i < 4; i++) s2[i] = 0ull;
        #pragma unroll 4
        for (int d = 0; d < 64; d++) {
            unsigned long long kb = *(const unsigned long long*)&Kt[d * 34 + 2 * p1];
            #pragma unroll
            for (int i = 0; i < 4; i++) {
                float qa = Qt[d * 65 + q0 + i];
                ffma2(s2[i], pack2(qa, qa), kb);
            }
        }
        const int mv0 = msk[2 * p1], mv1 = msk[2 * p1 + 1];
        #pragma unroll
        for (int i = 0; i < 4; i++) {
            float sx, sy;
            unpack2(s2[i], sx, sy);
            sx = (mv0 > 0) ? sx * scale : -1e9f;
            sy = (mv1 > 0) ? sy * scale : -1e9f;
            *(float2*)&Ps[(q0 + i) * 34 + 2 * p1] = make_float2(sx, sy);
        }
        __syncthreads();

        // ---- per-row online-softmax update (64 rows, 1 thread each) ----
        if (tid < 64) {
            float mold = m_s[tid];
            float mloc = -INFINITY;
            float* pr = &Ps[tid * 34];
            #pragma unroll
            for (int k = 0; k < 32; k++) mloc = fmaxf(mloc, pr[k]);
            float mnew = fmaxf(mold, mloc);
            float c = __expf(mold - mnew);     // 0 on first tile (mold = -inf)
            float ssum = 0.f;
            #pragma unroll
            for (int k = 0; k < 32; k++) {
                float p = __expf(pr[k] - mnew);
                pr[k] = p;
                ssum += p;
            }
            l_s[tid] = l_s[tid] * c + ssum;
            m_s[tid] = mnew;
            c_s[tid] = c;
        }
        __syncthreads();

        // ---- rescale accumulators, then PV accumulate ----
        #pragma unroll
        for (int i = 0; i < 4; i++) {
            float c = c_s[q0 + i];
            unsigned long long cc = pack2(c, c);
            o_acc[i][0] = fmul2(o_acc[i][0], cc);
            o_acc[i][1] = fmul2(o_acc[i][1], cc);
        }
        #pragma unroll 4
        for (int k = 0; k < 32; k++) {
            unsigned long long v0 = *(const unsigned long long*)&Vs[k * 64 + 2 * p1];
            unsigned long long v1 = *(const unsigned long long*)&Vs[k * 64 + 2 * p1 + 32];
            #pragma unroll
            for (int i = 0; i < 4; i++) {
                float p = Ps[(q0 + i) * 34 + k];
                unsigned long long pp = pack2(p, p);
                ffma2(o_acc[i][0], pp, v0);
                ffma2(o_acc[i][1], pp, v1);
            }
        }
    }
    __syncthreads();

    #pragma unroll
    for (int i = 0; i < 4; i++) {
        float inv = 1.f / l_s[q0 + i];
        int row = b * PT + qbase + q0 + i;
        float x, y;
        unpack2(o_acc[i][0], x, y);
        *(float2*)&g_att[row * PD + h * PDH + 2 * p1] = make_float2(x * inv, y * inv);
        unpack2(o_acc[i][1], x, y);
        *(float2*)&g_att[row * PD + h * PDH + 2 * p1 + 32] = make_float2(x * inv, y * inv);
    }
}

// =====================================================================
// Kernel 3: fusion GEMM  out[4096,1024] = g_att @ Wf + bf
//   grid = (D/128, (B*T)/64), block = 256, 64m x 128n block tile,
//   thread = 4m x 8n (4 f32x2), k-tiles of 32.
// =====================================================================
__global__ __launch_bounds__(256) void fuse_kernel(
    const float* __restrict__ Wf, const float* __restrict__ bf,
    float* __restrict__ out)
{
    __shared__ __align__(16) float As[32 * 65];   // [k][m]
    __shared__ __align__(16) float Bs[32 * 128];  // [k][n]

    const int tid   = threadIdx.x;
    const int nbase = blockIdx.x * 128;
    const int mbase = blockIdx.y * 64;
    const int m0 = (tid >> 4) << 2;
    const int n1 = tid & 15;

    unsigned long long acc[4][4];
    #pragma unroll
    for (int i = 0; i < 4; i++)
        #pragma unroll
        for (int j = 0; j < 4; j++) acc[i][j] = 0ull;

    for (int kt = 0; kt < 32; kt++) {
        __syncthreads();
        for (int i = tid; i < 2048; i += 256) {
            int m = i >> 5, k = i & 31;
            As[k * 65 + m] = g_att[(mbase + m) * PD + kt * 32 + k];
        }
        for (int i = tid; i < 4096; i += 256) {
            int k = i >> 7, n = i & 127;
            Bs[k * 128 + n] = Wf[(kt * 32 + k) * PD + nbase + n];
        }
        __syncthreads();

        #pragma unroll 8
        for (int k = 0; k < 32; k++) {
            unsigned long long b2[4];
            #pragma unroll
            for (int j = 0; j < 4; j++)
                b2[j] = *(const unsigned long long*)&Bs[k * 128 + 2 * n1 + 32 * j];
            #pragma unroll
            for (int i = 0; i < 4; i++) {
                float a = As[k * 65 + m0 + i];
                unsigned long long aa = pack2(a, a);
                #pragma unroll
                for (int j = 0; j < 4; j++) ffma2(acc[i][j], aa, b2[j]);
            }
        }
    }

    #pragma unroll
    for (int i = 0; i < 4; i++) {
        int row = mbase + m0 + i;
        #pragma unroll
        for (int j = 0; j < 4; j++) {
            int col = nbase + 2 * n1 + 32 * j;
            float x, y;
            unpack2(acc[i][j], x, y);
            *(float2*)&out[row * PD + col] = make_float2(x + bf[col], y + bf[col + 1]);
        }
    }
}

// =====================================================================
extern "C" void kernel_launch(void* const* d_in, const int* in_sizes, int n_in,
                              void* d_out, int out_size)
{
    const float* X    = (const float*)d_in[0];
    const int*   mask = (const int*)  d_in[1];
    const float* Wq   = (const float*)d_in[2];
    const float* bq   = (const float*)d_in[3];
    const float* Wk   = (const float*)d_in[4];
    const float* bk   = (const float*)d_in[5];
    const float* Wv   = (const float*)d_in[6];
    const float* bv   = (const float*)d_in[7];
    const float* Wf   = (const float*)d_in[8];
    const float* bf   = (const float*)d_in[9];
    float* out = (float*)d_out;

    qkv_kernel<<<dim3(PT / 64, PBH, 3), 256>>>(X, Wq, bq, Wk, bk, Wv, bv);
    attn_kernel<<<dim3(PT / 64, PBH), 256>>>(mask);
    fuse_kernel<<<dim3(PD / 128, (PB * PT) / 64), 256>>>(Wf, bf, out);
}

// round 2
// speedup vs baseline: 2.3898x; 2.3898x over previous
#include <cuda_runtime.h>
#include <math.h>

#define PB 8
#define PT 512
#define PD 1024
#define PH 16
#define PDH 64
#define PBH (PB*PH)

// Scratch (device globals: allocation-free)
__device__ float g_Q[PBH*PT*PDH];
__device__ float g_K[PBH*PT*PDH];
__device__ float g_V[PBH*PT*PDH];
__device__ float g_att[PB*PT*PD];
__device__ float g_Wf[PD*PD];

// ---------------- helpers ----------------
__device__ __forceinline__ float tf32r(float x) {
    float r; asm("cvt.rna.tf32.f32 %0, %1;" : "=f"(r) : "f"(x)); return r;
}
__device__ __forceinline__ unsigned fu(float x) { return __float_as_uint(x); }

// m16n8k8 tf32 mma. A row-major, B col-major, C/D fp32.
__device__ __forceinline__ void mma_tf32(float d[4], const unsigned a[4], const unsigned b[2]) {
    asm("mma.sync.aligned.m16n8k8.row.col.f32.tf32.tf32.f32 "
        "{%0,%1,%2,%3}, {%4,%5,%6,%7}, {%8,%9}, {%0,%1,%2,%3};"
        : "+f"(d[0]), "+f"(d[1]), "+f"(d[2]), "+f"(d[3])
        : "r"(a[0]), "r"(a[1]), "r"(a[2]), "r"(a[3]), "r"(b[0]), "r"(b[1]));
}

// =====================================================================
// Kernel 0: round Wf to tf32 once (so fuse kernel needs no cvt).
// =====================================================================
__global__ __launch_bounds__(256) void prep_kernel(const float* __restrict__ Wf) {
    int i = (blockIdx.x * 256 + threadIdx.x) * 4;
    float4 v = *(const float4*)&Wf[i];
    v.x = tf32r(v.x); v.y = tf32r(v.y); v.z = tf32r(v.z); v.w = tf32r(v.w);
    *(float4*)&g_Wf[i] = v;
}

// =====================================================================
// Kernel 1: fused Q/K/V projection, tf32 mma.
//   grid = (4096/64, 16 heads), block = 128 (4 warps, warp = 32m x 32n).
//   X tile loaded once; loop over {Wq,Wk,Wv}.
// =====================================================================
__global__ __launch_bounds__(128) void qkv_kernel(
    const float* __restrict__ X,
    const float* __restrict__ Wq, const float* __restrict__ bq,
    const float* __restrict__ Wk, const float* __restrict__ bk,
    const float* __restrict__ Wv, const float* __restrict__ bv)
{
    __shared__ float Xs[64 * 68];   // [m][d], stride 68 -> frag banks 4g+t
    __shared__ float Ws[64 * 72];   // [d][e], stride 72 -> frag banks 8t+g
    __shared__ float bs[64];

    const int tid = threadIdx.x, lane = tid & 31, wid = tid >> 5;
    const int g = lane >> 2, t = lane & 3;
    const int mtile = blockIdx.x, h = blockIdx.y;
    const int m0 = (wid >> 1) * 32, n0 = (wid & 1) * 32;

    for (int i = tid; i < 1024; i += 128) {
        int r = i >> 4, c4 = (i & 15) << 2;
        float4 v = *(const float4*)&X[(mtile * 64 + r) * PD + h * PDH + c4];
        v.x = tf32r(v.x); v.y = tf32r(v.y); v.z = tf32r(v.z); v.w = tf32r(v.w);
        *(float4*)&Xs[r * 68 + c4] = v;
    }

    const int b = mtile >> 3, t0 = (mtile & 7) * 64;

    #pragma unroll 1
    for (int which = 0; which < 3; which++) {
        const float* W  = (which == 0) ? Wq : (which == 1) ? Wk : Wv;
        const float* bi = (which == 0) ? bq : (which == 1) ? bk : bv;
        float* out      = (which == 0) ? g_Q : (which == 1) ? g_K : g_V;
        W  += h * PDH * PDH;
        bi += h * PDH;

        __syncthreads();  // previous phase done with Ws (and Xs load visible)
        for (int i = tid; i < 1024; i += 128) {
            int r = i >> 4, c4 = (i & 15) << 2;
            float4 v = *(const float4*)&W[r * PDH + c4];
            v.x = tf32r(v.x); v.y = tf32r(v.y); v.z = tf32r(v.z); v.w = tf32r(v.w);
            *(float4*)&Ws[r * 72 + c4] = v;
        }
        if (tid < 64) bs[tid] = bi[tid];
        __syncthreads();

        float acc[2][4][4];
        #pragma unroll
        for (int mi = 0; mi < 2; mi++)
            #pragma unroll
            for (int nj = 0; nj < 4; nj++)
                #pragma unroll
                for (int r = 0; r < 4; r++) acc[mi][nj][r] = 0.f;

        #pragma unroll
        for (int kk = 0; kk < 8; kk++) {
            int k0 = kk * 8;
            unsigned a[2][4];
            #pragma unroll
            for (int mi = 0; mi < 2; mi++) {
                int rr = m0 + 16 * mi + g;
                a[mi][0] = fu(Xs[rr * 68 + k0 + t]);
                a[mi][1] = fu(Xs[(rr + 8) * 68 + k0 + t]);
                a[mi][2] = fu(Xs[rr * 68 + k0 + t + 4]);
                a[mi][3] = fu(Xs[(rr + 8) * 68 + k0 + t + 4]);
            }
            #pragma unroll
            for (int nj = 0; nj < 4; nj++) {
                unsigned bb[2] = { fu(Ws[(k0 + t) * 72 + n0 + 8 * nj + g]),
                                   fu(Ws[(k0 + t + 4) * 72 + n0 + 8 * nj + g]) };
                #pragma unroll
                for (int mi = 0; mi < 2; mi++) mma_tf32(acc[mi][nj], a[mi], bb);
            }
        }

        #pragma unroll
        for (int mi = 0; mi < 2; mi++) {
            int row = m0 + 16 * mi + g;
            int base_row = ((b * PH + h) * PT + t0 + row) * PDH;
            #pragma unroll
            for (int nj = 0; nj < 4; nj++) {
                int col = n0 + 8 * nj + 2 * t;
                float2 v0 = make_float2(tf32r(acc[mi][nj][0] + bs[col]),
                                        tf32r(acc[mi][nj][1] + bs[col + 1]));
                *(float2*)&out[base_row + col] = v0;
                float2 v1 = make_float2(tf32r(acc[mi][nj][2] + bs[col]),
                                        tf32r(acc[mi][nj][3] + bs[col + 1]));
                *(float2*)&out[base_row + 8 * PDH + col] = v1;
            }
        }
    }
}

// =====================================================================
// Kernel 2: flash attention, tf32 mma, online softmax in fragments.
//   grid = (T/64, B*H), block = 128 (4 warps, warp owns 16 q-rows).
//   Q fragments preloaded to registers; P stays in registers (C->A via shfl).
// =====================================================================
__global__ __launch_bounds__(128) void attn_kernel(const int* __restrict__ mask)
{
    __shared__ float sK[64 * 68];   // first Q tile, then K tiles ([row][d], stride 68)
    __shared__ float sV[64 * 72];   // [kpos][e], stride 72
    __shared__ int   smsk[64];

    const int tid = threadIdx.x, lane = tid & 31, wid = tid >> 5;
    const int g = lane >> 2, t = lane & 3;
    const int qtile = blockIdx.x, bh = blockIdx.y;
    const int b = bh >> 4, h = bh & 15;
    const int qbase = qtile * 64, q0 = wid * 16;
    const unsigned FULL = 0xffffffffu;

    // ---- load Q tile, preload A fragments ----
    for (int i = tid; i < 1024; i += 128) {
        int r = i >> 4, c4 = (i & 15) << 2;
        *(float4*)&sK[r * 68 + c4] =
            *(const float4*)&g_Q[(bh * PT + qbase + r) * PDH + c4];
    }
    __syncthreads();
    unsigned qa[8][4];
    #pragma unroll
    for (int kk = 0; kk < 8; kk++) {
        int k0 = kk * 8;
        qa[kk][0] = fu(sK[(q0 + g) * 68 + k0 + t]);
        qa[kk][1] = fu(sK[(q0 + 8 + g) * 68 + k0 + t]);
        qa[kk][2] = fu(sK[(q0 + g) * 68 + k0 + t + 4]);
        qa[kk][3] = fu(sK[(q0 + 8 + g) * 68 + k0 + t + 4]);
    }

    float Oacc[8][4];
    #pragma unroll
    for (int j = 0; j < 8; j++)
        #pragma unroll
        for (int r = 0; r < 4; r++) Oacc[j][r] = 0.f;
    float m0r = -INFINITY, m1r = -INFINITY, l0r = 0.f, l1r = 0.f;

    for (int kt = 0; kt < 8; kt++) {
        __syncthreads();   // everyone done with sK (Q frags / prev K) and sV
        for (int i = tid; i < 1024; i += 128) {
            int r = i >> 4, c4 = (i & 15) << 2;
            *(float4*)&sK[r * 68 + c4] =
                *(const float4*)&g_K[(bh * PT + kt * 64 + r) * PDH + c4];
            *(float4*)&sV[r * 72 + c4] =
                *(const float4*)&g_V[(bh * PT + kt * 64 + r) * PDH + c4];
        }
        if (tid < 64) smsk[tid] = mask[b * PT + kt * 64 + tid];
        __syncthreads();

        // ---- S = Q @ K^T (16q x 64k per warp) ----
        float S[8][4];
        #pragma unroll
        for (int j = 0; j < 8; j++)
            #pragma unroll
            for (int r = 0; r < 4; r++) S[j][r] = 0.f;
        #pragma unroll
        for (int kk = 0; kk < 8; kk++) {
            int k0 = kk * 8;
            #pragma unroll
            for (int j = 0; j < 8; j++) {
                unsigned bb[2] = { fu(sK[(8 * j + g) * 68 + k0 + t]),
                                   fu(sK[(8 * j + g) * 68 + k0 + t + 4]) };
                mma_tf32(S[j], qa[kk], bb);
            }
        }

        // ---- scale + mask + row max ----
        float rmax0 = -INFINITY, rmax1 = -INFINITY;
        #pragma unroll
        for (int j = 0; j < 8; j++) {
            int c = 8 * j + 2 * t;
            bool mk0 = smsk[c] > 0, mk1 = smsk[c + 1] > 0;
            S[j][0] = mk0 ? S[j][0] * 0.125f : -1e9f;
            S[j][1] = mk1 ? S[j][1] * 0.125f : -1e9f;
            S[j][2] = mk0 ? S[j][2] * 0.125f : -1e9f;
            S[j][3] = mk1 ? S[j][3] * 0.125f : -1e9f;
            rmax0 = fmaxf(rmax0, fmaxf(S[j][0], S[j][1]));
            rmax1 = fmaxf(rmax1, fmaxf(S[j][2], S[j][3]));
        }
        rmax0 = fmaxf(rmax0, __shfl_xor_sync(FULL, rmax0, 1));
        rmax0 = fmaxf(rmax0, __shfl_xor_sync(FULL, rmax0, 2));
        rmax1 = fmaxf(rmax1, __shfl_xor_sync(FULL, rmax1, 1));
        rmax1 = fmaxf(rmax1, __shfl_xor_sync(FULL, rmax1, 2));

        float mn0 = fmaxf(m0r, rmax0), mn1 = fmaxf(m1r, rmax1);
        float c0 = __expf(m0r - mn0), c1 = __expf(m1r - mn1);
        m0r = mn0; m1r = mn1;

        float sum0 = 0.f, sum1 = 0.f;
        #pragma unroll
        for (int j = 0; j < 8; j++) {
            S[j][0] = __expf(S[j][0] - mn0);
            S[j][1] = __expf(S[j][1] - mn0);
            S[j][2] = __expf(S[j][2] - mn1);
            S[j][3] = __expf(S[j][3] - mn1);
            sum0 += S[j][0] + S[j][1];
            sum1 += S[j][2] + S[j][3];
            S[j][0] = tf32r(S[j][0]); S[j][1] = tf32r(S[j][1]);
            S[j][2] = tf32r(S[j][2]); S[j][3] = tf32r(S[j][3]);
        }
        sum0 += __shfl_xor_sync(FULL, sum0, 1);
        sum0 += __shfl_xor_sync(FULL, sum0, 2);
        sum1 += __shfl_xor_sync(FULL, sum1, 1);
        sum1 += __shfl_xor_sync(FULL, sum1, 2);
        l0r = l0r * c0 + sum0;
        l1r = l1r * c1 + sum1;
        #pragma unroll
        for (int j = 0; j < 8; j++) {
            Oacc[j][0] *= c0; Oacc[j][1] *= c0;
            Oacc[j][2] *= c1; Oacc[j][3] *= c1;
        }

        // ---- O += P @ V  (P: C-frag -> A-frag via shuffles) ----
        const int src1 = 4 * g + (t >> 1), src2 = src1 + 2;
        const bool odd = (t & 1);
        #pragma unroll
        for (int kk = 0; kk < 8; kk++) {
            float u0 = __shfl_sync(FULL, S[kk][0], src1);
            float u1 = __shfl_sync(FULL, S[kk][1], src1);
            float u2 = __shfl_sync(FULL, S[kk][2], src1);
            float u3 = __shfl_sync(FULL, S[kk][3], src1);
            float w0 = __shfl_sync(FULL, S[kk][0], src2);
            float w1 = __shfl_sync(FULL, S[kk][1], src2);
            float w2 = __shfl_sync(FULL, S[kk][2], src2);
            float w3 = __shfl_sync(FULL, S[kk][3], src2);
            unsigned a[4];
            a[0] = fu(odd ? u1 : u0);
            a[1] = fu(odd ? u3 : u2);
            a[2] = fu(odd ? w1 : w0);
            a[3] = fu(odd ? w3 : w2);
            int k0 = kk * 8;
            #pragma unroll
            for (int j = 0; j < 8; j++) {
                unsigned bb[2] = { fu(sV[(k0 + t) * 72 + 8 * j + g]),
                                   fu(sV[(k0 + t + 4) * 72 + 8 * j + g]) };
                mma_tf32(Oacc[j], a, bb);
            }
        }
    }

    // ---- epilogue: normalize, round for the fuse GEMM, store ----
    float inv0 = 1.f / l0r, inv1 = 1.f / l1r;
    int r0 = b * PT + qbase + q0 + g;
    #pragma unroll
    for (int j = 0; j < 8; j++) {
        int col = h * PDH + 8 * j + 2 * t;
        float2 v0 = make_float2(tf32r(Oacc[j][0] * inv0), tf32r(Oacc[j][1] * inv0));
        *(float2*)&g_att[r0 * PD + col] = v0;
        float2 v1 = make_float2(tf32r(Oacc[j][2] * inv1), tf32r(Oacc[j][3] * inv1));
        *(float2*)&g_att[(r0 + 8) * PD + col] = v1;
    }
}

// =====================================================================
// Kernel 3: fusion GEMM, tf32 mma.  out[4096,1024] = g_att @ g_Wf + bf.
//   grid = (1024/128, 4096/128), block = 256 (8 warps, warp = 64m x 32n).
// =====================================================================
__global__ __launch_bounds__(256) void fuse_kernel(
    const float* __restrict__ bf, float* __restrict__ out)
{
    __shared__ float sA[128 * 36];   // [m][k], stride 36 -> frag banks 4g+t
    __shared__ float sB[32 * 136];   // [k][n], stride 136 -> frag banks 8t+g

    const int tid = threadIdx.x, lane = tid & 31, wid = tid >> 5;
    const int g = lane >> 2, t = lane & 3;
    const int nbase = blockIdx.x * 128, mbase = blockIdx.y * 128;
    const int m0 = (wid >> 2) * 64, n0 = (wid & 3) * 32;

    float acc[4][4][4];
    #pragma unroll
    for (int mi = 0; mi < 4; mi++)
        #pragma unroll
        for (int nj = 0; nj < 4; nj++)
            #pragma unroll
            for (int r = 0; r < 4; r++) acc[mi][nj][r] = 0.f;

    for (int kt = 0; kt < 32; kt++) {
        __syncthreads();
        for (int i = tid; i < 1024; i += 256) {
            int r = i >> 3, c4 = (i & 7) << 2;
            *(float4*)&sA[r * 36 + c4] =
                *(const float4*)&g_att[(mbase + r) * PD + kt * 32 + c4];
        }
        for (int i = tid; i < 1024; i += 256) {
            int r = i >> 5, c4 = (i & 31) << 2;
            *(float4*)&sB[r * 136 + c4] =
                *(const float4*)&g_Wf[(kt * 32 + r) * PD + nbase + c4];
        }
        __syncthreads();

        #pragma unroll
        for (int kk = 0; kk < 4; kk++) {
            int k0 = kk * 8;
            unsigned a[4][4];
            #pragma unroll
            for (int mi = 0; mi < 4; mi++) {
                int rr = m0 + 16 * mi + g;
                a[mi][0] = fu(sA[rr * 36 + k0 + t]);
                a[mi][1] = fu(sA[(rr + 8) * 36 + k0 + t]);
                a[mi][2] = fu(sA[rr * 36 + k0 + t + 4]);
                a[mi][3] = fu(sA[(rr + 8) * 36 + k0 + t + 4]);
            }
            #pragma unroll
            for (int nj = 0; nj < 4; nj++) {
                unsigned bb[2] = { fu(sB[(k0 + t) * 136 + n0 + 8 * nj + g]),
                                   fu(sB[(k0 + t + 4) * 136 + n0 + 8 * nj + g]) };
                #pragma unroll
                for (int mi = 0; mi < 4; mi++) mma_tf32(acc[mi][nj], a[mi], bb);
            }
        }
    }

    #pragma unroll
    for (int mi = 0; mi < 4; mi++) {
        int row = mbase + m0 + 16 * mi + g;
        #pragma unroll
        for (int nj = 0; nj < 4; nj++) {
            int col = nbase + n0 + 8 * nj + 2 * t;
            float2 v0 = make_float2(acc[mi][nj][0] + bf[col],
                                    acc[mi][nj][1] + bf[col + 1]);
            *(float2*)&out[row * PD + col] = v0;
            float2 v1 = make_float2(acc[mi][nj][2] + bf[col],
                                    acc[mi][nj][3] + bf[col + 1]);
            *(float2*)&out[(row + 8) * PD + col] = v1;
        }
    }
}

// =====================================================================
extern "C" void kernel_launch(void* const* d_in, const int* in_sizes, int n_in,
                              void* d_out, int out_size)
{
    const float* X    = (const float*)d_in[0];
    const int*   mask = (const int*)  d_in[1];
    const float* Wq   = (const float*)d_in[2];
    const float* bq   = (const float*)d_in[3];
    const float* Wk   = (const float*)d_in[4];
    const float* bk   = (const float*)d_in[5];
    const float* Wv   = (const float*)d_in[6];
    const float* bv   = (const float*)d_in[7];
    const float* Wf   = (const float*)d_in[8];
    const float* bf   = (const float*)d_in[9];
    float* out = (float*)d_out;

    prep_kernel<<<1024, 256>>>(Wf);
    qkv_kernel<<<dim3(64, 16), 128>>>(X, Wq, bq, Wk, bk, Wv, bv);
    attn_kernel<<<dim3(PT / 64, PBH), 128>>>(mask);
    fuse_kernel<<<dim3(PD / 128, (PB * PT) / 128), 256>>>(bf, out);
}

// round 3
// speedup vs baseline: 3.0430x; 1.2733x over previous
#include <cuda_runtime.h>
#include <math.h>

#define PB 8
#define PT 512
#define PD 1024
#define PH 16
#define PDH 64
#define PBH (PB*PH)

// Scratch (device globals: allocation-free)
__device__ float g_Q[PBH*PT*PDH];
__device__ float g_K[PBH*PT*PDH];
__device__ float g_V[PBH*PT*PDH];
__device__ float g_att[PB*PT*PD];
__device__ float g_Wf[PD*PD];

// ---------------- helpers ----------------
__device__ __forceinline__ float tf32r(float x) {
    float r; asm("cvt.rna.tf32.f32 %0, %1;" : "=f"(r) : "f"(x)); return r;
}
__device__ __forceinline__ unsigned fu(float x) { return __float_as_uint(x); }

__device__ __forceinline__ void mma_tf32(float d[4], const unsigned a[4], const unsigned b[2]) {
    asm("mma.sync.aligned.m16n8k8.row.col.f32.tf32.tf32.f32 "
        "{%0,%1,%2,%3}, {%4,%5,%6,%7}, {%8,%9}, {%0,%1,%2,%3};"
        : "+f"(d[0]), "+f"(d[1]), "+f"(d[2]), "+f"(d[3])
        : "r"(a[0]), "r"(a[1]), "r"(a[2]), "r"(a[3]), "r"(b[0]), "r"(b[1]));
}

__device__ __forceinline__ void cp16(unsigned s, const void* g) {
    asm volatile("cp.async.cg.shared.global [%0], [%1], 16;" :: "r"(s), "l"(g));
}
__device__ __forceinline__ void cp_commit() {
    asm volatile("cp.async.commit_group;");
}
template<int N> __device__ __forceinline__ void cp_wait() {
    asm volatile("cp.async.wait_group %0;" :: "n"(N));
}

// =====================================================================
// Kernel 0: round Wf to tf32 once.
// =====================================================================
__global__ __launch_bounds__(256) void prep_kernel(const float* __restrict__ Wf) {
    int i = (blockIdx.x * 256 + threadIdx.x) * 4;
    float4 v = *(const float4*)&Wf[i];
    v.x = tf32r(v.x); v.y = tf32r(v.y); v.z = tf32r(v.z); v.w = tf32r(v.w);
    *(float4*)&g_Wf[i] = v;
}

// =====================================================================
// Kernel 1: fused Q/K/V projection (unchanged from R2).
// =====================================================================
__global__ __launch_bounds__(128) void qkv_kernel(
    const float* __restrict__ X,
    const float* __restrict__ Wq, const float* __restrict__ bq,
    const float* __restrict__ Wk, const float* __restrict__ bk,
    const float* __restrict__ Wv, const float* __restrict__ bv)
{
    __shared__ float Xs[64 * 68];
    __shared__ float Ws[64 * 72];
    __shared__ float bs[64];

    const int tid = threadIdx.x, lane = tid & 31, wid = tid >> 5;
    const int g = lane >> 2, t = lane & 3;
    const int mtile = blockIdx.x, h = blockIdx.y;
    const int m0 = (wid >> 1) * 32, n0 = (wid & 1) * 32;

    for (int i = tid; i < 1024; i += 128) {
        int r = i >> 4, c4 = (i & 15) << 2;
        float4 v = *(const float4*)&X[(mtile * 64 + r) * PD + h * PDH + c4];
        v.x = tf32r(v.x); v.y = tf32r(v.y); v.z = tf32r(v.z); v.w = tf32r(v.w);
        *(float4*)&Xs[r * 68 + c4] = v;
    }

    const int b = mtile >> 3, t0 = (mtile & 7) * 64;

    #pragma unroll 1
    for (int which = 0; which < 3; which++) {
        const float* W  = (which == 0) ? Wq : (which == 1) ? Wk : Wv;
        const float* bi = (which == 0) ? bq : (which == 1) ? bk : bv;
        float* out      = (which == 0) ? g_Q : (which == 1) ? g_K : g_V;
        W  += h * PDH * PDH;
        bi += h * PDH;

        __syncthreads();
        for (int i = tid; i < 1024; i += 128) {
            int r = i >> 4, c4 = (i & 15) << 2;
            float4 v = *(const float4*)&W[r * PDH + c4];
            v.x = tf32r(v.x); v.y = tf32r(v.y); v.z = tf32r(v.z); v.w = tf32r(v.w);
            *(float4*)&Ws[r * 72 + c4] = v;
        }
        if (tid < 64) bs[tid] = bi[tid];
        __syncthreads();

        float acc[2][4][4];
        #pragma unroll
        for (int mi = 0; mi < 2; mi++)
            #pragma unroll
            for (int nj = 0; nj < 4; nj++)
                #pragma unroll
                for (int r = 0; r < 4; r++) acc[mi][nj][r] = 0.f;

        #pragma unroll
        for (int kk = 0; kk < 8; kk++) {
            int k0 = kk * 8;
            unsigned a[2][4];
            #pragma unroll
            for (int mi = 0; mi < 2; mi++) {
                int rr = m0 + 16 * mi + g;
                a[mi][0] = fu(Xs[rr * 68 + k0 + t]);
                a[mi][1] = fu(Xs[(rr + 8) * 68 + k0 + t]);
                a[mi][2] = fu(Xs[rr * 68 + k0 + t + 4]);
                a[mi][3] = fu(Xs[(rr + 8) * 68 + k0 + t + 4]);
            }
            #pragma unroll
            for (int nj = 0; nj < 4; nj++) {
                unsigned bb[2] = { fu(Ws[(k0 + t) * 72 + n0 + 8 * nj + g]),
                                   fu(Ws[(k0 + t + 4) * 72 + n0 + 8 * nj + g]) };
                #pragma unroll
                for (int mi = 0; mi < 2; mi++) mma_tf32(acc[mi][nj], a[mi], bb);
            }
        }

        #pragma unroll
        for (int mi = 0; mi < 2; mi++) {
            int row = m0 + 16 * mi + g;
            int base_row = ((b * PH + h) * PT + t0 + row) * PDH;
            #pragma unroll
            for (int nj = 0; nj < 4; nj++) {
                int col = n0 + 8 * nj + 2 * t;
                float2 v0 = make_float2(tf32r(acc[mi][nj][0] + bs[col]),
                                        tf32r(acc[mi][nj][1] + bs[col + 1]));
                *(float2*)&out[base_row + col] = v0;
                float2 v1 = make_float2(tf32r(acc[mi][nj][2] + bs[col]),
                                        tf32r(acc[mi][nj][3] + bs[col + 1]));
                *(float2*)&out[base_row + 8 * PDH + col] = v1;
            }
        }
    }
}

// =====================================================================
// Kernel 2: flash attention, cp.async 2-stage pipeline, KV chunks of 32.
//   grid = (T/64, B*H), block = 128 (4 warps, warp owns 16 q-rows).
// =====================================================================
__global__ __launch_bounds__(128) void attn_kernel(const int* __restrict__ mask)
{
    __shared__ float sK[2][32 * 68];   // [kpos][d] stride 68; also Q staging
    __shared__ float sV[2][32 * 72];   // [kpos][e] stride 72
    __shared__ int   smsk[512];

    const int tid = threadIdx.x, lane = tid & 31, wid = tid >> 5;
    const int g = lane >> 2, t = lane & 3;
    const int qtile = blockIdx.x, bh = blockIdx.y;
    const int b = bh >> 4, h = bh & 15;
    const int qbase = qtile * 64;
    const unsigned FULL = 0xffffffffu;

    // ---- stage Q tile into the two K buffers, read A fragments ----
    for (int i = tid; i < 1024; i += 128) {
        int r = i >> 4, c4 = (i & 15) << 2;   // r in [0,64)
        *(float4*)&sK[r >> 5][(r & 31) * 68 + c4] =
            *(const float4*)&g_Q[(bh * PT + qbase + r) * PDH + c4];
    }
    for (int i = tid; i < 512; i += 128) smsk[i] = mask[b * PT + i];
    __syncthreads();

    unsigned qa[8][4];
    {
        const float* qb = sK[wid >> 1];
        int lr = (wid & 1) * 16 + g;           // local row in the 32-row buffer
        #pragma unroll
        for (int kk = 0; kk < 8; kk++) {
            int k0 = kk * 8;
            qa[kk][0] = fu(qb[lr * 68 + k0 + t]);
            qa[kk][1] = fu(qb[(lr + 8) * 68 + k0 + t]);
            qa[kk][2] = fu(qb[lr * 68 + k0 + t + 4]);
            qa[kk][3] = fu(qb[(lr + 8) * 68 + k0 + t + 4]);
        }
    }
    __syncthreads();   // Q frags read before prefetch overwrites buffers

    const float* Kbase = &g_K[bh * PT * PDH];
    const float* Vbase = &g_V[bh * PT * PDH];

    // prefetch tile 0
    {
        #pragma unroll
        for (int p = 0; p < 4; p++) {
            int i = tid + p * 128;             // 512 float4s
            int r = i >> 4, c4 = (i & 15) << 2;
            cp16((unsigned)__cvta_generic_to_shared(&sK[0][r * 68 + c4]),
                 &Kbase[r * PDH + c4]);
            cp16((unsigned)__cvta_generic_to_shared(&sV[0][r * 72 + c4]),
                 &Vbase[r * PDH + c4]);
        }
        cp_commit();
    }

    float Oacc[8][4];
    #pragma unroll
    for (int j = 0; j < 8; j++)
        #pragma unroll
        for (int r = 0; r < 4; r++) Oacc[j][r] = 0.f;
    float m0r = -INFINITY, m1r = -INFINITY, l0r = 0.f, l1r = 0.f;

    for (int kt = 0; kt < 16; kt++) {
        const int buf = kt & 1;
        if (kt < 15) {
            const float* Kn = &Kbase[(kt + 1) * 32 * PDH];
            const float* Vn = &Vbase[(kt + 1) * 32 * PDH];
            #pragma unroll
            for (int p = 0; p < 4; p++) {
                int i = tid + p * 128;
                int r = i >> 4, c4 = (i & 15) << 2;
                cp16((unsigned)__cvta_generic_to_shared(&sK[buf ^ 1][r * 68 + c4]),
                     &Kn[r * PDH + c4]);
                cp16((unsigned)__cvta_generic_to_shared(&sV[buf ^ 1][r * 72 + c4]),
                     &Vn[r * PDH + c4]);
            }
        }
        cp_commit();
        cp_wait<1>();
        __syncthreads();

        // ---- S = Q @ K^T (16q x 32k per warp) ----
        float S[4][4];
        #pragma unroll
        for (int j = 0; j < 4; j++)
            #pragma unroll
            for (int r = 0; r < 4; r++) S[j][r] = 0.f;
        #pragma unroll
        for (int kk = 0; kk < 8; kk++) {
            int k0 = kk * 8;
            #pragma unroll
            for (int j = 0; j < 4; j++) {
                unsigned bb[2] = { fu(sK[buf][(8 * j + g) * 68 + k0 + t]),
                                   fu(sK[buf][(8 * j + g) * 68 + k0 + t + 4]) };
                mma_tf32(S[j], qa[kk], bb);
            }
        }

        // ---- scale + mask + row max ----
        float rmax0 = -INFINITY, rmax1 = -INFINITY;
        #pragma unroll
        for (int j = 0; j < 4; j++) {
            int c = kt * 32 + 8 * j + 2 * t;
            bool mk0 = smsk[c] > 0, mk1 = smsk[c + 1] > 0;
            S[j][0] = mk0 ? S[j][0] * 0.125f : -1e9f;
            S[j][1] = mk1 ? S[j][1] * 0.125f : -1e9f;
            S[j][2] = mk0 ? S[j][2] * 0.125f : -1e9f;
            S[j][3] = mk1 ? S[j][3] * 0.125f : -1e9f;
            rmax0 = fmaxf(rmax0, fmaxf(S[j][0], S[j][1]));
            rmax1 = fmaxf(rmax1, fmaxf(S[j][2], S[j][3]));
        }
        rmax0 = fmaxf(rmax0, __shfl_xor_sync(FULL, rmax0, 1));
        rmax0 = fmaxf(rmax0, __shfl_xor_sync(FULL, rmax0, 2));
        rmax1 = fmaxf(rmax1, __shfl_xor_sync(FULL, rmax1, 1));
        rmax1 = fmaxf(rmax1, __shfl_xor_sync(FULL, rmax1, 2));

        float mn0 = fmaxf(m0r, rmax0), mn1 = fmaxf(m1r, rmax1);
        float c0 = __expf(m0r - mn0), c1 = __expf(m1r - mn1);
        m0r = mn0; m1r = mn1;

        float sum0 = 0.f, sum1 = 0.f;
        #pragma unroll
        for (int j = 0; j < 4; j++) {
            S[j][0] = __expf(S[j][0] - mn0);
            S[j][1] = __expf(S[j][1] - mn0);
            S[j][2] = __expf(S[j][2] - mn1);
            S[j][3] = __expf(S[j][3] - mn1);
            sum0 += S[j][0] + S[j][1];
            sum1 += S[j][2] + S[j][3];
            S[j][0] = tf32r(S[j][0]); S[j][1] = tf32r(S[j][1]);
            S[j][2] = tf32r(S[j][2]); S[j][3] = tf32r(S[j][3]);
        }
        sum0 += __shfl_xor_sync(FULL, sum0, 1);
        sum0 += __shfl_xor_sync(FULL, sum0, 2);
        sum1 += __shfl_xor_sync(FULL, sum1, 1);
        sum1 += __shfl_xor_sync(FULL, sum1, 2);
        l0r = l0r * c0 + sum0;
        l1r = l1r * c1 + sum1;
        #pragma unroll
        for (int j = 0; j < 8; j++) {
            Oacc[j][0] *= c0; Oacc[j][1] *= c0;
            Oacc[j][2] *= c1; Oacc[j][3] *= c1;
        }

        // ---- O += P @ V  (P: C-frag -> A-frag via shuffles) ----
        const int src1 = 4 * g + (t >> 1), src2 = src1 + 2;
        const bool odd = (t & 1);
        #pragma unroll
        for (int kk = 0; kk < 4; kk++) {
            float u0 = __shfl_sync(FULL, S[kk][0], src1);
            float u1 = __shfl_sync(FULL, S[kk][1], src1);
            float u2 = __shfl_sync(FULL, S[kk][2], src1);
            float u3 = __shfl_sync(FULL, S[kk][3], src1);
            float w0 = __shfl_sync(FULL, S[kk][0], src2);
            float w1 = __shfl_sync(FULL, S[kk][1], src2);
            float w2 = __shfl_sync(FULL, S[kk][2], src2);
            float w3 = __shfl_sync(FULL, S[kk][3], src2);
            unsigned a[4];
            a[0] = fu(odd ? u1 : u0);
            a[1] = fu(odd ? u3 : u2);
            a[2] = fu(odd ? w1 : w0);
            a[3] = fu(odd ? w3 : w2);
            int k0 = kk * 8;
            #pragma unroll
            for (int j = 0; j < 8; j++) {
                unsigned bb[2] = { fu(sV[buf][(k0 + t) * 72 + 8 * j + g]),
                                   fu(sV[buf][(k0 + t + 4) * 72 + 8 * j + g]) };
                mma_tf32(Oacc[j], a, bb);
            }
        }
        __syncthreads();   // done with buf before it is overwritten
    }

    // ---- epilogue ----
    float inv0 = 1.f / l0r, inv1 = 1.f / l1r;
    int r0 = b * PT + qbase + wid * 16 + g;
    #pragma unroll
    for (int j = 0; j < 8; j++) {
        int col = h * PDH + 8 * j + 2 * t;
        float2 v0 = make_float2(tf32r(Oacc[j][0] * inv0), tf32r(Oacc[j][1] * inv0));
        *(float2*)&g_att[r0 * PD + col] = v0;
        float2 v1 = make_float2(tf32r(Oacc[j][2] * inv1), tf32r(Oacc[j][3] * inv1));
        *(float2*)&g_att[(r0 + 8) * PD + col] = v1;
    }
}

// =====================================================================
// Kernel 3: fusion GEMM, cp.async 2-stage, BK=16.
//   grid = (8, 32), block = 256 (8 warps, warp = 64m x 32n), tile 128x128.
//   sA [m][k] stride 20 (banks 20g+t: conflict-free)
//   sB [k][n] stride 132 (banks 4t+g: conflict-free)
// =====================================================================
__global__ __launch_bounds__(256) void fuse_kernel(
    const float* __restrict__ bf, float* __restrict__ out)
{
    __shared__ float sA[2][128 * 20];
    __shared__ float sB[2][16 * 132];

    const int tid = threadIdx.x, lane = tid & 31, wid = tid >> 5;
    const int g = lane >> 2, t = lane & 3;
    const int nbase = blockIdx.x * 128, mbase = blockIdx.y * 128;
    const int m0 = (wid >> 2) * 64, n0 = (wid & 3) * 32;

    const float* Ab = &g_att[mbase * PD];
    const float* Bb = &g_Wf[nbase];

    // per-thread load slots (4 float4 each: 2 for A, 2 for B)
    const int ia0 = tid, ia1 = tid + 256;            // A: 512 float4
    const int ib0 = tid, ib1 = tid + 256;            // B: 512 float4

    // prefetch kt = 0
    {
        #pragma unroll
        for (int p = 0; p < 2; p++) {
            int i = (p == 0) ? ia0 : ia1;
            int r = i >> 2, c4 = (i & 3) << 2;
            cp16((unsigned)__cvta_generic_to_shared(&sA[0][r * 20 + c4]),
                 &Ab[r * PD + c4]);
        }
        #pragma unroll
        for (int p = 0; p < 2; p++) {
            int i = (p == 0) ? ib0 : ib1;
            int r = i >> 5, c4 = (i & 31) << 2;
            cp16((unsigned)__cvta_generic_to_shared(&sB[0][r * 132 + c4]),
                 &Bb[r * PD + c4]);
        }
        cp_commit();
    }

    float acc[4][4][4];
    #pragma unroll
    for (int mi = 0; mi < 4; mi++)
        #pragma unroll
        for (int nj = 0; nj < 4; nj++)
            #pragma unroll
            for (int r = 0; r < 4; r++) acc[mi][nj][r] = 0.f;

    for (int kt = 0; kt < 64; kt++) {
        const int buf = kt & 1;
        if (kt < 63) {
            const float* An = Ab + (kt + 1) * 16;
            const float* Bn = Bb + (kt + 1) * 16 * PD;
            #pragma unroll
            for (int p = 0; p < 2; p++) {
                int i = (p == 0) ? ia0 : ia1;
                int r = i >> 2, c4 = (i & 3) << 2;
                cp16((unsigned)__cvta_generic_to_shared(&sA[buf ^ 1][r * 20 + c4]),
                     &An[r * PD + c4]);
            }
            #pragma unroll
            for (int p = 0; p < 2; p++) {
                int i = (p == 0) ? ib0 : ib1;
                int r = i >> 5, c4 = (i & 31) << 2;
                cp16((unsigned)__cvta_generic_to_shared(&sB[buf ^ 1][r * 132 + c4]),
                     &Bn[r * PD + c4]);
            }
        }
        cp_commit();
        cp_wait<1>();
        __syncthreads();

        #pragma unroll
        for (int kk = 0; kk < 2; kk++) {
            int k0 = kk * 8;
            unsigned a[4][4];
            #pragma unroll
            for (int mi = 0; mi < 4; mi++) {
                int rr = m0 + 16 * mi + g;
                a[mi][0] = fu(sA[buf][rr * 20 + k0 + t]);
                a[mi][1] = fu(sA[buf][(rr + 8) * 20 + k0 + t]);
                a[mi][2] = fu(sA[buf][rr * 20 + k0 + t + 4]);
                a[mi][3] = fu(sA[buf][(rr + 8) * 20 + k0 + t + 4]);
            }
            #pragma unroll
            for (int nj = 0; nj < 4; nj++) {
                unsigned bb[2] = { fu(sB[buf][(k0 + t) * 132 + n0 + 8 * nj + g]),
                                   fu(sB[buf][(k0 + t + 4) * 132 + n0 + 8 * nj + g]) };
                #pragma unroll
                for (int mi = 0; mi < 4; mi++) mma_tf32(acc[mi][nj], a[mi], bb);
            }
        }
        __syncthreads();
    }

    #pragma unroll
    for (int mi = 0; mi < 4; mi++) {
        int row = mbase + m0 + 16 * mi + g;
        #pragma unroll
        for (int nj = 0; nj < 4; nj++) {
            int col = nbase + n0 + 8 * nj + 2 * t;
            float2 v0 = make_float2(acc[mi][nj][0] + bf[col],
                                    acc[mi][nj][1] + bf[col + 1]);
            *(float2*)&out[row * PD + col] = v0;
            float2 v1 = make_float2(acc[mi][nj][2] + bf[col],
                                    acc[mi][nj][3] + bf[col + 1]);
            *(float2*)&out[(row + 8) * PD + col] = v1;
        }
    }
}

// =====================================================================
extern "C" void kernel_launch(void* const* d_in, const int* in_sizes, int n_in,
                              void* d_out, int out_size)
{
    const float* X    = (const float*)d_in[0];
    const int*   mask = (const int*)  d_in[1];
    const float* Wq   = (const float*)d_in[2];
    const float* bq   = (const float*)d_in[3];
    const float* Wk   = (const float*)d_in[4];
    const float* bk   = (const float*)d_in[5];
    const float* Wv   = (const float*)d_in[6];
    const float* bv   = (const float*)d_in[7];
    const float* Wf   = (const float*)d_in[8];
    const float* bf   = (const float*)d_in[9];
    float* out = (float*)d_out;

    prep_kernel<<<1024, 256>>>(Wf);
    qkv_kernel<<<dim3(64, 16), 128>>>(X, Wq, bq, Wk, bk, Wv, bv);
    attn_kernel<<<dim3(PT / 64, PBH), 128>>>(mask);
    fuse_kernel<<<dim3(PD / 128, (PB * PT) / 128), 256>>>(bf, out);
}

// round 5
// speedup vs baseline: 3.2839x; 1.0792x over previous
#include <cuda_runtime.h>
#include <math.h>

#define PB 8
#define PT 512
#define PD 1024
#define PH 16
#define PDH 64
#define PBH (PB*PH)

// Scratch (device globals: allocation-free)
__device__ float g_Q[PBH*PT*PDH];
__device__ float g_K[PBH*PT*PDH];
__device__ float g_V[PBH*PT*PDH];
__device__ float g_att[PB*PT*PD];
__device__ float g_Wf[PD*PD];

// ---------------- helpers ----------------
__device__ __forceinline__ float tf32r(float x) {
    float r; asm("cvt.rna.tf32.f32 %0, %1;" : "=f"(r) : "f"(x)); return r;
}
__device__ __forceinline__ unsigned fu(float x) { return __float_as_uint(x); }

__device__ __forceinline__ void mma_tf32(float d[4], const unsigned a[4], const unsigned b[2]) {
    asm("mma.sync.aligned.m16n8k8.row.col.f32.tf32.tf32.f32 "
        "{%0,%1,%2,%3}, {%4,%5,%6,%7}, {%8,%9}, {%0,%1,%2,%3};"
        : "+f"(d[0]), "+f"(d[1]), "+f"(d[2]), "+f"(d[3])
        : "r"(a[0]), "r"(a[1]), "r"(a[2]), "r"(a[3]), "r"(b[0]), "r"(b[1]));
}

__device__ __forceinline__ void cp16(unsigned s, const void* g) {
    asm volatile("cp.async.cg.shared.global [%0], [%1], 16;" :: "r"(s), "l"(g));
}
__device__ __forceinline__ void cp_commit() {
    asm volatile("cp.async.commit_group;");
}
template<int N> __device__ __forceinline__ void cp_wait() {
    asm volatile("cp.async.wait_group %0;" :: "n"(N));
}

// =====================================================================
// Kernel 0: round Wf to tf32 once.
// =====================================================================
__global__ __launch_bounds__(256) void prep_kernel(const float* __restrict__ Wf) {
    int i = (blockIdx.x * 256 + threadIdx.x) * 4;
    float4 v = *(const float4*)&Wf[i];
    v.x = tf32r(v.x); v.y = tf32r(v.y); v.z = tf32r(v.z); v.w = tf32r(v.w);
    *(float4*)&g_Wf[i] = v;
}

// =====================================================================
// Kernel 1: fused Q/K/V projection (as R2/R3).
// =====================================================================
__global__ __launch_bounds__(128) void qkv_kernel(
    const float* __restrict__ X,
    const float* __restrict__ Wq, const float* __restrict__ bq,
    const float* __restrict__ Wk, const float* __restrict__ bk,
    const float* __restrict__ Wv, const float* __restrict__ bv)
{
    __shared__ float Xs[64 * 68];
    __shared__ float Ws[64 * 72];
    __shared__ float bs[64];

    const int tid = threadIdx.x, lane = tid & 31, wid = tid >> 5;
    const int g = lane >> 2, t = lane & 3;
    const int mtile = blockIdx.x, h = blockIdx.y;
    const int m0 = (wid >> 1) * 32, n0 = (wid & 1) * 32;

    for (int i = tid; i < 1024; i += 128) {
        int r = i >> 4, c4 = (i & 15) << 2;
        float4 v = *(const float4*)&X[(mtile * 64 + r) * PD + h * PDH + c4];
        v.x = tf32r(v.x); v.y = tf32r(v.y); v.z = tf32r(v.z); v.w = tf32r(v.w);
        *(float4*)&Xs[r * 68 + c4] = v;
    }

    const int b = mtile >> 3, t0 = (mtile & 7) * 64;

    #pragma unroll 1
    for (int which = 0; which < 3; which++) {
        const float* W  = (which == 0) ? Wq : (which == 1) ? Wk : Wv;
        const float* bi = (which == 0) ? bq : (which == 1) ? bk : bv;
        float* out      = (which == 0) ? g_Q : (which == 1) ? g_K : g_V;
        W  += h * PDH * PDH;
        bi += h * PDH;

        __syncthreads();
        for (int i = tid; i < 1024; i += 128) {
            int r = i >> 4, c4 = (i & 15) << 2;
            float4 v = *(const float4*)&W[r * PDH + c4];
            v.x = tf32r(v.x); v.y = tf32r(v.y); v.z = tf32r(v.z); v.w = tf32r(v.w);
            *(float4*)&Ws[r * 72 + c4] = v;
        }
        if (tid < 64) bs[tid] = bi[tid];
        __syncthreads();

        float acc[2][4][4];
        #pragma unroll
        for (int mi = 0; mi < 2; mi++)
            #pragma unroll
            for (int nj = 0; nj < 4; nj++)
                #pragma unroll
                for (int r = 0; r < 4; r++) acc[mi][nj][r] = 0.f;

        #pragma unroll
        for (int kk = 0; kk < 8; kk++) {
            int k0 = kk * 8;
            unsigned a[2][4];
            #pragma unroll
            for (int mi = 0; mi < 2; mi++) {
                int rr = m0 + 16 * mi + g;
                a[mi][0] = fu(Xs[rr * 68 + k0 + t]);
                a[mi][1] = fu(Xs[(rr + 8) * 68 + k0 + t]);
                a[mi][2] = fu(Xs[rr * 68 + k0 + t + 4]);
                a[mi][3] = fu(Xs[(rr + 8) * 68 + k0 + t + 4]);
            }
            #pragma unroll
            for (int nj = 0; nj < 4; nj++) {
                unsigned bb[2] = { fu(Ws[(k0 + t) * 72 + n0 + 8 * nj + g]),
                                   fu(Ws[(k0 + t + 4) * 72 + n0 + 8 * nj + g]) };
                #pragma unroll
                for (int mi = 0; mi < 2; mi++) mma_tf32(acc[mi][nj], a[mi], bb);
            }
        }

        #pragma unroll
        for (int mi = 0; mi < 2; mi++) {
            int row = m0 + 16 * mi + g;
            int base_row = ((b * PH + h) * PT + t0 + row) * PDH;
            #pragma unroll
            for (int nj = 0; nj < 4; nj++) {
                int col = n0 + 8 * nj + 2 * t;
                float2 v0 = make_float2(tf32r(acc[mi][nj][0] + bs[col]),
                                        tf32r(acc[mi][nj][1] + bs[col + 1]));
                *(float2*)&out[base_row + col] = v0;
                float2 v1 = make_float2(tf32r(acc[mi][nj][2] + bs[col]),
                                        tf32r(acc[mi][nj][3] + bs[col + 1]));
                *(float2*)&out[base_row + 8 * PDH + col] = v1;
            }
        }
    }
}

// =====================================================================
// Kernel 2: flash attention, 64-key chunks, cp.async 2-stage.
//   grid = (T/64, B*H), block = 128 (4 warps, warp owns 16 q-rows).
//   Dynamic smem: sK 2 bufs stride 68, sV 2 bufs stride 72, mask.
//   KST=68 (banks 4g+t conflict-free), VST=72 (banks 8t+g conflict-free).
// =====================================================================
#define KST 68
#define VST 72
#define KBUF (64 * KST)
#define VBUF (64 * VST)
#define ATTN_SMEM ((2 * KBUF + 2 * VBUF + 512) * 4)

__global__ __launch_bounds__(128) void attn_kernel(const int* __restrict__ mask)
{
    extern __shared__ float asm_[];
    float* sK0 = asm_;
    float* sK1 = asm_ + KBUF;
    float* sV0 = asm_ + 2 * KBUF;
    float* sV1 = asm_ + 2 * KBUF + VBUF;
    int*   smsk = (int*)(asm_ + 2 * KBUF + 2 * VBUF);

    const int tid = threadIdx.x, lane = tid & 31, wid = tid >> 5;
    const int g = lane >> 2, t = lane & 3;
    const int qtile = blockIdx.x, bh = blockIdx.y;
    const int b = bh >> 4, h = bh & 15;
    const int qbase = qtile * 64;
    const unsigned FULL = 0xffffffffu;

    // ---- stage Q tile in sK0, extract A fragments ----
    for (int i = tid; i < 1024; i += 128) {
        int r = i >> 4, c4 = (i & 15) << 2;
        *(float4*)&sK0[r * KST + c4] =
            *(const float4*)&g_Q[(bh * PT + qbase + r) * PDH + c4];
    }
    for (int i = tid; i < 512; i += 128) smsk[i] = mask[b * PT + i];
    __syncthreads();

    unsigned qa[8][4];
    {
        const int q0 = wid * 16;
        #pragma unroll
        for (int kk = 0; kk < 8; kk++) {
            int k0 = kk * 8;
            qa[kk][0] = fu(sK0[(q0 + g) * KST + k0 + t]);
            qa[kk][1] = fu(sK0[(q0 + 8 + g) * KST + k0 + t]);
            qa[kk][2] = fu(sK0[(q0 + g) * KST + k0 + t + 4]);
            qa[kk][3] = fu(sK0[(q0 + 8 + g) * KST + k0 + t + 4]);
        }
    }
    __syncthreads();   // Q frags read before prefetch overwrites sK0

    const float* Kbase = &g_K[bh * PT * PDH];
    const float* Vbase = &g_V[bh * PT * PDH];

    // prefetch chunk 0 (64 rows K + 64 rows V = 2048 float4)
    {
        #pragma unroll
        for (int p = 0; p < 8; p++) {
            int i = tid + p * 128;
            int r = i >> 4, c4 = (i & 15) << 2;
            cp16((unsigned)__cvta_generic_to_shared(&sK0[r * KST + c4]),
                 &Kbase[r * PDH + c4]);
            cp16((unsigned)__cvta_generic_to_shared(&sV0[r * VST + c4]),
                 &Vbase[r * PDH + c4]);
        }
        cp_commit();
    }

    float Oacc[8][4];
    #pragma unroll
    for (int j = 0; j < 8; j++)
        #pragma unroll
        for (int r = 0; r < 4; r++) Oacc[j][r] = 0.f;
    float m0r = -INFINITY, m1r = -INFINITY, l0r = 0.f, l1r = 0.f;

    for (int kt = 0; kt < 8; kt++) {
        float* cK = (kt & 1) ? sK1 : sK0;
        float* cV = (kt & 1) ? sV1 : sV0;
        float* nK = (kt & 1) ? sK0 : sK1;
        float* nV = (kt & 1) ? sV0 : sV1;
        if (kt < 7) {
            const float* Kn = &Kbase[(kt + 1) * 64 * PDH];
            const float* Vn = &Vbase[(kt + 1) * 64 * PDH];
            #pragma unroll
            for (int p = 0; p < 8; p++) {
                int i = tid + p * 128;
                int r = i >> 4, c4 = (i & 15) << 2;
                cp16((unsigned)__cvta_generic_to_shared(&nK[r * KST + c4]),
                     &Kn[r * PDH + c4]);
                cp16((unsigned)__cvta_generic_to_shared(&nV[r * VST + c4]),
                     &Vn[r * PDH + c4]);
            }
        }
        cp_commit();
        cp_wait<1>();
        __syncthreads();

        // ---- S = Q @ K^T (16q x 64k per warp) ----
        float S[8][4];
        #pragma unroll
        for (int j = 0; j < 8; j++)
            #pragma unroll
            for (int r = 0; r < 4; r++) S[j][r] = 0.f;
        #pragma unroll
        for (int kk = 0; kk < 8; kk++) {
            int k0 = kk * 8;
            #pragma unroll
            for (int j = 0; j < 8; j++) {
                unsigned bb[2] = { fu(cK[(8 * j + g) * KST + k0 + t]),
                                   fu(cK[(8 * j + g) * KST + k0 + t + 4]) };
                mma_tf32(S[j], qa[kk], bb);
            }
        }

        // ---- scale + mask + row max ----
        float rmax0 = -INFINITY, rmax1 = -INFINITY;
        #pragma unroll
        for (int j = 0; j < 8; j++) {
            int c = kt * 64 + 8 * j + 2 * t;
            bool mk0 = smsk[c] > 0, mk1 = smsk[c + 1] > 0;
            S[j][0] = mk0 ? S[j][0] * 0.125f : -1e9f;
            S[j][1] = mk1 ? S[j][1] * 0.125f : -1e9f;
            S[j][2] = mk0 ? S[j][2] * 0.125f : -1e9f;
            S[j][3] = mk1 ? S[j][3] * 0.125f : -1e9f;
            rmax0 = fmaxf(rmax0, fmaxf(S[j][0], S[j][1]));
            rmax1 = fmaxf(rmax1, fmaxf(S[j][2], S[j][3]));
        }
        rmax0 = fmaxf(rmax0, __shfl_xor_sync(FULL, rmax0, 1));
        rmax0 = fmaxf(rmax0, __shfl_xor_sync(FULL, rmax0, 2));
        rmax1 = fmaxf(rmax1, __shfl_xor_sync(FULL, rmax1, 1));
        rmax1 = fmaxf(rmax1, __shfl_xor_sync(FULL, rmax1, 2));

        float mn0 = fmaxf(m0r, rmax0), mn1 = fmaxf(m1r, rmax1);
        float c0 = __expf(m0r - mn0), c1 = __expf(m1r - mn1);
        m0r = mn0; m1r = mn1;

        float sum0 = 0.f, sum1 = 0.f;
        #pragma unroll
        for (int j = 0; j < 8; j++) {
            S[j][0] = __expf(S[j][0] - mn0);
            S[j][1] = __expf(S[j][1] - mn0);
            S[j][2] = __expf(S[j][2] - mn1);
            S[j][3] = __expf(S[j][3] - mn1);
            sum0 += S[j][0] + S[j][1];
            sum1 += S[j][2] + S[j][3];
            S[j][0] = tf32r(S[j][0]); S[j][1] = tf32r(S[j][1]);
            S[j][2] = tf32r(S[j][2]); S[j][3] = tf32r(S[j][3]);
        }
        sum0 += __shfl_xor_sync(FULL, sum0, 1);
        sum0 += __shfl_xor_sync(FULL, sum0, 2);
        sum1 += __shfl_xor_sync(FULL, sum1, 1);
        sum1 += __shfl_xor_sync(FULL, sum1, 2);
        l0r = l0r * c0 + sum0;
        l1r = l1r * c1 + sum1;
        #pragma unroll
        for (int j = 0; j < 8; j++) {
            Oacc[j][0] *= c0; Oacc[j][1] *= c0;
            Oacc[j][2] *= c1; Oacc[j][3] *= c1;
        }

        // ---- O += P @ V  (P: C-frag -> A-frag via shuffles) ----
        const int src1 = 4 * g + (t >> 1), src2 = src1 + 2;
        const bool odd = (t & 1);
        #pragma unroll
        for (int kk = 0; kk < 8; kk++) {
            float u0 = __shfl_sync(FULL, S[kk][0], src1);
            float u1 = __shfl_sync(FULL, S[kk][1], src1);
            float u2 = __shfl_sync(FULL, S[kk][2], src1);
            float u3 = __shfl_sync(FULL, S[kk][3], src1);
            float w0 = __shfl_sync(FULL, S[kk][0], src2);
            float w1 = __shfl_sync(FULL, S[kk][1], src2);
            float w2 = __shfl_sync(FULL, S[kk][2], src2);
            float w3 = __shfl_sync(FULL, S[kk][3], src2);
            unsigned a[4];
            a[0] = fu(odd ? u1 : u0);
            a[1] = fu(odd ? u3 : u2);
            a[2] = fu(odd ? w1 : w0);
            a[3] = fu(odd ? w3 : w2);
            int k0 = kk * 8;
            #pragma unroll
            for (int j = 0; j < 8; j++) {
                unsigned bb[2] = { fu(cV[(k0 + t) * VST + 8 * j + g]),
                                   fu(cV[(k0 + t + 4) * VST + 8 * j + g]) };
                mma_tf32(Oacc[j], a, bb);
            }
        }
        __syncthreads();   // done with cK/cV before next iter's prefetch
    }

    // ---- epilogue ----
    float inv0 = 1.f / l0r, inv1 = 1.f / l1r;
    int r0 = b * PT + qbase + wid * 16 + g;
    #pragma unroll
    for (int j = 0; j < 8; j++) {
        int col = h * PDH + 8 * j + 2 * t;
        float2 v0 = make_float2(tf32r(Oacc[j][0] * inv0), tf32r(Oacc[j][1] * inv0));
        *(float2*)&g_att[r0 * PD + col] = v0;
        float2 v1 = make_float2(tf32r(Oacc[j][2] * inv1), tf32r(Oacc[j][3] * inv1));
        *(float2*)&g_att[(r0 + 8) * PD + col] = v1;
    }
}

// =====================================================================
// Kernel 3: fusion GEMM, cp.async 3-stage, BK=16, ONE sync per tile.
//   grid = (8, 32), block = 256 (8 warps, warp = 64m x 32n), tile 128x128.
//   sA [m][k] stride 20 (banks 20g+t), sB [k][n] stride 136 (banks 8t+g).
// =====================================================================
#define FA (128 * 20)
#define FB (16 * 136)
#define FUSE_SMEM ((3 * (FA + FB)) * 4)

__global__ __launch_bounds__(256) void fuse_kernel(
    const float* __restrict__ bf, float* __restrict__ out)
{
    extern __shared__ float dsm[];
    float* sA = dsm;             // 3 stages of FA
    float* sB = dsm + 3 * FA;    // 3 stages of FB

    const int tid = threadIdx.x, lane = tid & 31, wid = tid >> 5;
    const int g = lane >> 2, t = lane & 3;
    const int nbase = blockIdx.x * 128, mbase = blockIdx.y * 128;
    const int m0 = (wid >> 2) * 64, n0 = (wid & 3) * 32;

    const float* Ab = &g_att[mbase * PD];
    const float* Bb = &g_Wf[nbase];

    const int ra0 = tid >> 2,         ca0 = (tid & 3) << 2;
    const int ra1 = (tid >> 2) + 64,  ca1 = ca0;
    const int rb0 = tid >> 5,         cb0 = (tid & 31) << 2;
    const int rb1 = (tid >> 5) + 8,   cb1 = cb0;

    // prefetch stages 0,1
    #pragma unroll
    for (int s = 0; s < 2; s++) {
        const float* An = Ab + s * 16;
        const float* Bn = Bb + s * 16 * PD;
        cp16((unsigned)__cvta_generic_to_shared(&sA[s * FA + ra0 * 20 + ca0]),
             &An[ra0 * PD + ca0]);
        cp16((unsigned)__cvta_generic_to_shared(&sA[s * FA + ra1 * 20 + ca1]),
             &An[ra1 * PD + ca1]);
        cp16((unsigned)__cvta_generic_to_shared(&sB[s * FB + rb0 * 136 + cb0]),
             &Bn[rb0 * PD + cb0]);
        cp16((unsigned)__cvta_generic_to_shared(&sB[s * FB + rb1 * 136 + cb1]),
             &Bn[rb1 * PD + cb1]);
        cp_commit();
    }

    float acc[4][4][4];
    #pragma unroll
    for (int mi = 0; mi < 4; mi++)
        #pragma unroll
        for (int nj = 0; nj < 4; nj++)
            #pragma unroll
            for (int r = 0; r < 4; r++) acc[mi][nj][r] = 0.f;

    int sc = 0, sp = 2;   // compute stage, prefetch stage
    for (int kt = 0; kt < 64; kt++) {
        cp_wait<1>();
        __syncthreads();

        if (kt + 2 < 64) {
            const float* An = Ab + (kt + 2) * 16;
            const float* Bn = Bb + (kt + 2) * 16 * PD;
            cp16((unsigned)__cvta_generic_to_shared(&sA[sp * FA + ra0 * 20 + ca0]),
                 &An[ra0 * PD + ca0]);
            cp16((unsigned)__cvta_generic_to_shared(&sA[sp * FA + ra1 * 20 + ca1]),
                 &An[ra1 * PD + ca1]);
            cp16((unsigned)__cvta_generic_to_shared(&sB[sp * FB + rb0 * 136 + cb0]),
                 &Bn[rb0 * PD + cb0]);
            cp16((unsigned)__cvta_generic_to_shared(&sB[sp * FB + rb1 * 136 + cb1]),
                 &Bn[rb1 * PD + cb1]);
        }
        cp_commit();

        const float* cA = &sA[sc * FA];
        const float* cB = &sB[sc * FB];
        #pragma unroll
        for (int kk = 0; kk < 2; kk++) {
            int k0 = kk * 8;
            unsigned a[4][4];
            #pragma unroll
            for (int mi = 0; mi < 4; mi++) {
                int rr = m0 + 16 * mi + g;
                a[mi][0] = fu(cA[rr * 20 + k0 + t]);
                a[mi][1] = fu(cA[(rr + 8) * 20 + k0 + t]);
                a[mi][2] = fu(cA[rr * 20 + k0 + t + 4]);
                a[mi][3] = fu(cA[(rr + 8) * 20 + k0 + t + 4]);
            }
            #pragma unroll
            for (int nj = 0; nj < 4; nj++) {
                unsigned bb[2] = { fu(cB[(k0 + t) * 136 + n0 + 8 * nj + g]),
                                   fu(cB[(k0 + t + 4) * 136 + n0 + 8 * nj + g]) };
                #pragma unroll
                for (int mi = 0; mi < 4; mi++) mma_tf32(acc[mi][nj], a[mi], bb);
            }
        }
        sc = (sc == 2) ? 0 : sc + 1;
        sp = (sp == 2) ? 0 : sp + 1;
    }

    #pragma unroll
    for (int mi = 0; mi < 4; mi++) {
        int row = mbase + m0 + 16 * mi + g;
        #pragma unroll
        for (int nj = 0; nj < 4; nj++) {
            int col = nbase + n0 + 8 * nj + 2 * t;
            float2 v0 = make_float2(acc[mi][nj][0] + bf[col],
                                    acc[mi][nj][1] + bf[col + 1]);
            *(float2*)&out[row * PD + col] = v0;
            float2 v1 = make_float2(acc[mi][nj][2] + bf[col],
                                    acc[mi][nj][3] + bf[col + 1]);
            *(float2*)&out[(row + 8) * PD + col] = v1;
        }
    }
}

// =====================================================================
extern "C" void kernel_launch(void* const* d_in, const int* in_sizes, int n_in,
                              void* d_out, int out_size)
{
    const float* X    = (const float*)d_in[0];
    const int*   mask = (const int*)  d_in[1];
    const float* Wq   = (const float*)d_in[2];
    const float* bq   = (const float*)d_in[3];
    const float* Wk   = (const float*)d_in[4];
    const float* bk   = (const float*)d_in[5];
    const float* Wv   = (const float*)d_in[6];
    const float* bv   = (const float*)d_in[7];
    const float* Wf   = (const float*)d_in[8];
    const float* bf   = (const float*)d_in[9];
    float* out = (float*)d_out;

    cudaFuncSetAttribute(attn_kernel,
                         cudaFuncAttributeMaxDynamicSharedMemorySize, ATTN_SMEM);
    cudaFuncSetAttribute(fuse_kernel,
                         cudaFuncAttributeMaxDynamicSharedMemorySize, FUSE_SMEM);

    prep_kernel<<<1024, 256>>>(Wf);
    qkv_kernel<<<dim3(64, 16), 128>>>(X, Wq, bq, Wk, bk, Wv, bv);
    attn_kernel<<<dim3(PT / 64, PBH), 128, ATTN_SMEM>>>(mask);
    fuse_kernel<<<dim3(PD / 128, (PB * PT) / 128), 256, FUSE_SMEM>>>(bf, out);
}

// round 8
// speedup vs baseline: 3.5739x; 1.0883x over previous
#include <cuda_runtime.h>
#include <math.h>

#define PB 8
#define PT 512
#define PD 1024
#define PH 16
#define PDH 64
#define PBH (PB*PH)

// Scratch (device globals: allocation-free)
__device__ float g_Q[PBH*PT*PDH];
__device__ float g_K[PBH*PT*PDH];
__device__ float g_V[PBH*PT*PDH];
__device__ float g_att[PB*PT*PD];
__device__ float g_Wf[PD*PD];

// ---------------- helpers ----------------
__device__ __forceinline__ float tf32r(float x) {
    float r; asm("cvt.rna.tf32.f32 %0, %1;" : "=f"(r) : "f"(x)); return r;
}
__device__ __forceinline__ unsigned fu(float x) { return __float_as_uint(x); }
__device__ __forceinline__ float ex2(float x) {
    float r; asm("ex2.approx.ftz.f32 %0, %1;" : "=f"(r) : "f"(x)); return r;
}

__device__ __forceinline__ void mma_tf32(float d[4], const unsigned a[4], const unsigned b[2]) {
    asm("mma.sync.aligned.m16n8k8.row.col.f32.tf32.tf32.f32 "
        "{%0,%1,%2,%3}, {%4,%5,%6,%7}, {%8,%9}, {%0,%1,%2,%3};"
        : "+f"(d[0]), "+f"(d[1]), "+f"(d[2]), "+f"(d[3])
        : "r"(a[0]), "r"(a[1]), "r"(a[2]), "r"(a[3]), "r"(b[0]), "r"(b[1]));
}

__device__ __forceinline__ void ldm_x4(unsigned a[4], unsigned addr) {
    asm volatile("ldmatrix.sync.aligned.m8n8.x4.shared.b16 {%0,%1,%2,%3}, [%4];"
        : "=r"(a[0]), "=r"(a[1]), "=r"(a[2]), "=r"(a[3]) : "r"(addr));
}

__device__ __forceinline__ void cp16(unsigned s, const void* g) {
    asm volatile("cp.async.cg.shared.global [%0], [%1], 16;" :: "r"(s), "l"(g));
}
__device__ __forceinline__ void cp_commit() {
    asm volatile("cp.async.commit_group;");
}
template<int N> __device__ __forceinline__ void cp_wait() {
    asm volatile("cp.async.wait_group %0;" :: "n"(N));
}

// =====================================================================
// Kernel 0: round Wf to tf32 once.
// =====================================================================
__global__ __launch_bounds__(256) void prep_kernel(const float* __restrict__ Wf) {
    int i = (blockIdx.x * 256 + threadIdx.x) * 4;
    float4 v = *(const float4*)&Wf[i];
    v.x = tf32r(v.x); v.y = tf32r(v.y); v.z = tf32r(v.z); v.w = tf32r(v.w);
    *(float4*)&g_Wf[i] = v;
}

// =====================================================================
// Kernel 1: fused Q/K/V projection (unchanged; small).
// =====================================================================
__global__ __launch_bounds__(128) void qkv_kernel(
    const float* __restrict__ X,
    const float* __restrict__ Wq, const float* __restrict__ bq,
    const float* __restrict__ Wk, const float* __restrict__ bk,
    const float* __restrict__ Wv, const float* __restrict__ bv)
{
    __shared__ float Xs[64 * 68];
    __shared__ float Ws[64 * 72];
    __shared__ float bs[64];

    const int tid = threadIdx.x, lane = tid & 31, wid = tid >> 5;
    const int g = lane >> 2, t = lane & 3;
    const int mtile = blockIdx.x, h = blockIdx.y;
    const int m0 = (wid >> 1) * 32, n0 = (wid & 1) * 32;

    for (int i = tid; i < 1024; i += 128) {
        int r = i >> 4, c4 = (i & 15) << 2;
        float4 v = *(const float4*)&X[(mtile * 64 + r) * PD + h * PDH + c4];
        v.x = tf32r(v.x); v.y = tf32r(v.y); v.z = tf32r(v.z); v.w = tf32r(v.w);
        *(float4*)&Xs[r * 68 + c4] = v;
    }

    const int b = mtile >> 3, t0 = (mtile & 7) * 64;

    #pragma unroll 1
    for (int which = 0; which < 3; which++) {
        const float* W  = (which == 0) ? Wq : (which == 1) ? Wk : Wv;
        const float* bi = (which == 0) ? bq : (which == 1) ? bk : bv;
        float* out      = (which == 0) ? g_Q : (which == 1) ? g_K : g_V;
        W  += h * PDH * PDH;
        bi += h * PDH;

        __syncthreads();
        for (int i = tid; i < 1024; i += 128) {
            int r = i >> 4, c4 = (i & 15) << 2;
            float4 v = *(const float4*)&W[r * PDH + c4];
            v.x = tf32r(v.x); v.y = tf32r(v.y); v.z = tf32r(v.z); v.w = tf32r(v.w);
            *(float4*)&Ws[r * 72 + c4] = v;
        }
        if (tid < 64) bs[tid] = bi[tid];
        __syncthreads();

        float acc[2][4][4];
        #pragma unroll
        for (int mi = 0; mi < 2; mi++)
            #pragma unroll
            for (int nj = 0; nj < 4; nj++)
                #pragma unroll
                for (int r = 0; r < 4; r++) acc[mi][nj][r] = 0.f;

        #pragma unroll
        for (int kk = 0; kk < 8; kk++) {
            int k0 = kk * 8;
            unsigned a[2][4];
            #pragma unroll
            for (int mi = 0; mi < 2; mi++) {
                int rr = m0 + 16 * mi + g;
                a[mi][0] = fu(Xs[rr * 68 + k0 + t]);
                a[mi][1] = fu(Xs[(rr + 8) * 68 + k0 + t]);
                a[mi][2] = fu(Xs[rr * 68 + k0 + t + 4]);
                a[mi][3] = fu(Xs[(rr + 8) * 68 + k0 + t + 4]);
            }
            #pragma unroll
            for (int nj = 0; nj < 4; nj++) {
                unsigned bb[2] = { fu(Ws[(k0 + t) * 72 + n0 + 8 * nj + g]),
                                   fu(Ws[(k0 + t + 4) * 72 + n0 + 8 * nj + g]) };
                #pragma unroll
                for (int mi = 0; mi < 2; mi++) mma_tf32(acc[mi][nj], a[mi], bb);
            }
        }

        #pragma unroll
        for (int mi = 0; mi < 2; mi++) {
            int row = m0 + 16 * mi + g;
            int base_row = ((b * PH + h) * PT + t0 + row) * PDH;
            #pragma unroll
            for (int nj = 0; nj < 4; nj++) {
                int col = n0 + 8 * nj + 2 * t;
                float2 v0 = make_float2(tf32r(acc[mi][nj][0] + bs[col]),
                                        tf32r(acc[mi][nj][1] + bs[col + 1]));
                *(float2*)&out[base_row + col] = v0;
                float2 v1 = make_float2(tf32r(acc[mi][nj][2] + bs[col]),
                                        tf32r(acc[mi][nj][3] + bs[col + 1]));
                *(float2*)&out[base_row + 8 * PDH + col] = v1;
            }
        }
    }
}

// =====================================================================
// Kernel 2: flash attention, 64-key chunks, cp.async double buffer,
//   ldmatrix K-fragments, ONE barrier per chunk.
//   grid = (T/64, B*H), block = 128 (4 warps, warp owns 16 q-rows).
// =====================================================================
#define KST 68
#define VST 72
#define KBUF (64 * KST)
#define VBUF (64 * VST)
#define ATTN_SMEM ((2 * KBUF + 2 * VBUF + 512) * 4)

__global__ __launch_bounds__(128) void attn_kernel(const int* __restrict__ mask)
{
    extern __shared__ float asm_[];
    float* sK0 = asm_;
    float* sK1 = asm_ + KBUF;
    float* sV0 = asm_ + 2 * KBUF;
    float* sV1 = asm_ + 2 * KBUF + VBUF;
    int*   smsk = (int*)(asm_ + 2 * KBUF + 2 * VBUF);

    const int tid = threadIdx.x, lane = tid & 31, wid = tid >> 5;
    const int g = lane >> 2, t = lane & 3;
    const int qtile = blockIdx.x, bh = blockIdx.y;
    const int b = bh >> 4, h = bh & 15;
    const int qbase = qtile * 64;
    const unsigned FULL = 0xffffffffu;
    // scale * log2(e): softmax computed in base-2 domain
    const float SC2 = 0.125f * 1.44269504088896f;

    // ---- stage Q tile in sK0, extract A fragments ----
    for (int i = tid; i < 1024; i += 128) {
        int r = i >> 4, c4 = (i & 15) << 2;
        *(float4*)&sK0[r * KST + c4] =
            *(const float4*)&g_Q[(bh * PT + qbase + r) * PDH + c4];
    }
    for (int i = tid; i < 512; i += 128) smsk[i] = mask[b * PT + i];
    __syncthreads();

    unsigned qa[8][4];
    {
        const int q0 = wid * 16;
        #pragma unroll
        for (int kk = 0; kk < 8; kk++) {
            int k0 = kk * 8;
            qa[kk][0] = fu(sK0[(q0 + g) * KST + k0 + t]);
            qa[kk][1] = fu(sK0[(q0 + 8 + g) * KST + k0 + t]);
            qa[kk][2] = fu(sK0[(q0 + g) * KST + k0 + t + 4]);
            qa[kk][3] = fu(sK0[(q0 + 8 + g) * KST + k0 + t + 4]);
        }
    }
    __syncthreads();   // Q frags read before prefetch overwrites sK0

    const float* Kbase = &g_K[bh * PT * PDH];
    const float* Vbase = &g_V[bh * PT * PDH];

    // prefetch chunk 0
    {
        #pragma unroll
        for (int p = 0; p < 8; p++) {
            int i = tid + p * 128;
            int r = i >> 4, c4 = (i & 15) << 2;
            cp16((unsigned)__cvta_generic_to_shared(&sK0[r * KST + c4]),
                 &Kbase[r * PDH + c4]);
            cp16((unsigned)__cvta_generic_to_shared(&sV0[r * VST + c4]),
                 &Vbase[r * PDH + c4]);
        }
        cp_commit();
    }

    // ldmatrix lane base for K (rows (lane&15), col-half select on lane>=16)
    const unsigned kBase0 = (unsigned)__cvta_generic_to_shared(sK0);
    const unsigned kLaneOff = ((lane & 15) * KST + ((lane >> 4) << 2)) * 4u;

    float Oacc[8][4];
    #pragma unroll
    for (int j = 0; j < 8; j++)
        #pragma unroll
        for (int r = 0; r < 4; r++) Oacc[j][r] = 0.f;
    float m0r = -INFINITY, m1r = -INFINITY, l0r = 0.f, l1r = 0.f;

    for (int kt = 0; kt < 8; kt++) {
        cp_wait<0>();
        __syncthreads();   // chunk kt visible to all; all done with kt-1

        float* cV = (kt & 1) ? sV1 : sV0;
        const unsigned kBufAddr = kBase0 + (kt & 1) * (KBUF * 4u) + kLaneOff;

        if (kt < 7) {
            float* nK = (kt & 1) ? sK0 : sK1;
            float* nV = (kt & 1) ? sV0 : sV1;
            const float* Kn = &Kbase[(kt + 1) * 64 * PDH];
            const float* Vn = &Vbase[(kt + 1) * 64 * PDH];
            #pragma unroll
            for (int p = 0; p < 8; p++) {
                int i = tid + p * 128;
                int r = i >> 4, c4 = (i & 15) << 2;
                cp16((unsigned)__cvta_generic_to_shared(&nK[r * KST + c4]),
                     &Kn[r * PDH + c4]);
                cp16((unsigned)__cvta_generic_to_shared(&nV[r * VST + c4]),
                     &Vn[r * PDH + c4]);
            }
            cp_commit();
        }

        // ---- S = Q @ K^T (16q x 64k per warp), K frags via ldmatrix.x4 ----
        float S[8][4];
        #pragma unroll
        for (int j = 0; j < 8; j++)
            #pragma unroll
            for (int r = 0; r < 4; r++) S[j][r] = 0.f;
        #pragma unroll
        for (int kk = 0; kk < 8; kk++) {
            #pragma unroll
            for (int jp = 0; jp < 4; jp++) {
                unsigned kb[4];
                ldm_x4(kb, kBufAddr + (16 * jp * KST + 8 * kk) * 4u);
                unsigned b0[2] = { kb[0], kb[2] };
                unsigned b1[2] = { kb[1], kb[3] };
                mma_tf32(S[2 * jp],     qa[kk], b0);
                mma_tf32(S[2 * jp + 1], qa[kk], b1);
            }
        }

        // ---- scale(+log2e) + mask + row max ----
        float rmax0 = -INFINITY, rmax1 = -INFINITY;
        #pragma unroll
        for (int j = 0; j < 8; j++) {
            int c = kt * 64 + 8 * j + 2 * t;
            bool mk0 = smsk[c] > 0, mk1 = smsk[c + 1] > 0;
            S[j][0] = mk0 ? S[j][0] * SC2 : -1e9f;
            S[j][1] = mk1 ? S[j][1] * SC2 : -1e9f;
            S[j][2] = mk0 ? S[j][2] * SC2 : -1e9f;
            S[j][3] = mk1 ? S[j][3] * SC2 : -1e9f;
            rmax0 = fmaxf(rmax0, fmaxf(S[j][0], S[j][1]));
            rmax1 = fmaxf(rmax1, fmaxf(S[j][2], S[j][3]));
        }
        rmax0 = fmaxf(rmax0, __shfl_xor_sync(FULL, rmax0, 1));
        rmax0 = fmaxf(rmax0, __shfl_xor_sync(FULL, rmax0, 2));
        rmax1 = fmaxf(rmax1, __shfl_xor_sync(FULL, rmax1, 1));
        rmax1 = fmaxf(rmax1, __shfl_xor_sync(FULL, rmax1, 2));

        float mn0 = fmaxf(m0r, rmax0), mn1 = fmaxf(m1r, rmax1);
        float c0 = ex2(m0r - mn0), c1 = ex2(m1r - mn1);
        m0r = mn0; m1r = mn1;

        float sum0 = 0.f, sum1 = 0.f;
        #pragma unroll
        for (int j = 0; j < 8; j++) {
            S[j][0] = ex2(S[j][0] - mn0);
            S[j][1] = ex2(S[j][1] - mn0);
            S[j][2] = ex2(S[j][2] - mn1);
            S[j][3] = ex2(S[j][3] - mn1);
            sum0 += S[j][0] + S[j][1];
            sum1 += S[j][2] + S[j][3];
            S[j][0] = tf32r(S[j][0]); S[j][1] = tf32r(S[j][1]);
            S[j][2] = tf32r(S[j][2]); S[j][3] = tf32r(S[j][3]);
        }
        sum0 += __shfl_xor_sync(FULL, sum0, 1);
        sum0 += __shfl_xor_sync(FULL, sum0, 2);
        sum1 += __shfl_xor_sync(FULL, sum1, 1);
        sum1 += __shfl_xor_sync(FULL, sum1, 2);
        l0r = l0r * c0 + sum0;
        l1r = l1r * c1 + sum1;
        #pragma unroll
        for (int j = 0; j < 8; j++) {
            Oacc[j][0] *= c0; Oacc[j][1] *= c0;
            Oacc[j][2] *= c1; Oacc[j][3] *= c1;
        }

        // ---- O += P @ V  (P: C-frag -> A-frag via shuffles) ----
        const int src1 = 4 * g + (t >> 1), src2 = src1 + 2;
        const bool odd = (t & 1);
        #pragma unroll
        for (int kk = 0; kk < 8; kk++) {
            float u0 = __shfl_sync(FULL, S[kk][0], src1);
            float u1 = __shfl_sync(FULL, S[kk][1], src1);
            float u2 = __shfl_sync(FULL, S[kk][2], src1);
            float u3 = __shfl_sync(FULL, S[kk][3], src1);
            float w0 = __shfl_sync(FULL, S[kk][0], src2);
            float w1 = __shfl_sync(FULL, S[kk][1], src2);
            float w2 = __shfl_sync(FULL, S[kk][2], src2);
            float w3 = __shfl_sync(FULL, S[kk][3], src2);
            unsigned a[4];
            a[0] = fu(odd ? u1 : u0);
            a[1] = fu(odd ? u3 : u2);
            a[2] = fu(odd ? w1 : w0);
            a[3] = fu(odd ? w3 : w2);
            int k0 = kk * 8;
            #pragma unroll
            for (int j = 0; j < 8; j++) {
                unsigned bb[2] = { fu(cV[(k0 + t) * VST + 8 * j + g]),
                                   fu(cV[(k0 + t + 4) * VST + 8 * j + g]) };
                mma_tf32(Oacc[j], a, bb);
            }
        }
    }

    // ---- epilogue ----
    float inv0 = 1.f / l0r, inv1 = 1.f / l1r;
    int r0 = b * PT + qbase + wid * 16 + g;
    #pragma unroll
    for (int j = 0; j < 8; j++) {
        int col = h * PDH + 8 * j + 2 * t;
        float2 v0 = make_float2(tf32r(Oacc[j][0] * inv0), tf32r(Oacc[j][1] * inv0));
        *(float2*)&g_att[r0 * PD + col] = v0;
        float2 v1 = make_float2(tf32r(Oacc[j][2] * inv1), tf32r(Oacc[j][3] * inv1));
        *(float2*)&g_att[(r0 + 8) * PD + col] = v1;
    }
}

// =====================================================================
// Kernel 3: fusion GEMM, cp.async 3-stage, BK=32, ldmatrix A-frags.
//   grid = (8, 32), block = 256 (8 warps, warp = 64m x 32n), tile 128x128.
//   sA [m][k] stride 36 (ldmatrix rows conflict-free),
//   sB [k][n] stride 136 (banks 8t+g conflict-free).
//   Dynamic smem: 3*(128*36 + 32*136)*4 = 107520 B.
// =====================================================================
#define FA (128 * 36)
#define FB (32 * 136)
#define FUSE_SMEM ((3 * (FA + FB)) * 4)

__global__ __launch_bounds__(256, 2) void fuse_kernel(
    const float* __restrict__ bf, float* __restrict__ out)
{
    extern __shared__ float dsm[];
    float* sA = dsm;             // 3 stages of FA
    float* sB = dsm + 3 * FA;    // 3 stages of FB

    const int tid = threadIdx.x, lane = tid & 31, wid = tid >> 5;
    const int g = lane >> 2, t = lane & 3;
    const int nbase = blockIdx.x * 128, mbase = blockIdx.y * 128;
    const int m0 = (wid >> 2) * 64, n0 = (wid & 3) * 32;

    const float* Ab = &g_att[mbase * PD];
    const float* Bb = &g_Wf[nbase];

    // prefetch indexing: A 1024 float4/stage (4/thread), B 1024 float4/stage
    // A: r = i>>3 (0..127), c4 = (i&7)<<2 ; B: r = i>>5 (0..31), c4 = (i&31)<<2
    // prefetch stages 0,1
    #pragma unroll
    for (int s = 0; s < 2; s++) {
        const float* An = Ab + s * 32;
        const float* Bn = Bb + s * 32 * PD;
        #pragma unroll
        for (int p = 0; p < 4; p++) {
            int i = tid + p * 256;
            int r = i >> 3, c4 = (i & 7) << 2;
            cp16((unsigned)__cvta_generic_to_shared(&sA[s * FA + r * 36 + c4]),
                 &An[r * PD + c4]);
        }
        #pragma unroll
        for (int p = 0; p < 4; p++) {
            int i = tid + p * 256;
            int r = i >> 5, c4 = (i & 31) << 2;
            cp16((unsigned)__cvta_generic_to_shared(&sB[s * FB + r * 136 + c4]),
                 &Bn[r * PD + c4]);
        }
        cp_commit();
    }

    // ldmatrix lane base for A
    const unsigned aBase = (unsigned)__cvta_generic_to_shared(sA) +
                           ((m0 + (lane & 15)) * 36 + ((lane >> 4) << 2)) * 4u;

    float acc[4][4][4];
    #pragma unroll
    for (int mi = 0; mi < 4; mi++)
        #pragma unroll
        for (int nj = 0; nj < 4; nj++)
            #pragma unroll
            for (int r = 0; r < 4; r++) acc[mi][nj][r] = 0.f;

    int sc = 0, sp = 2;   // compute stage, prefetch stage
    for (int kt = 0; kt < 32; kt++) {
        cp_wait<1>();
        __syncthreads();

        if (kt + 2 < 32) {
            const float* An = Ab + (kt + 2) * 32;
            const float* Bn = Bb + (kt + 2) * 32 * PD;
            #pragma unroll
            for (int p = 0; p < 4; p++) {
                int i = tid + p * 256;
                int r = i >> 3, c4 = (i & 7) << 2;
                cp16((unsigned)__cvta_generic_to_shared(&sA[sp * FA + r * 36 + c4]),
                     &An[r * PD + c4]);
            }
            #pragma unroll
            for (int p = 0; p < 4; p++) {
                int i = tid + p * 256;
                int r = i >> 5, c4 = (i & 31) << 2;
                cp16((unsigned)__cvta_generic_to_shared(&sB[sp * FB + r * 136 + c4]),
                     &Bn[r * PD + c4]);
            }
        }
        cp_commit();

        const unsigned aStage = aBase + sc * (FA * 4u);
        const float* cB = &sB[sc * FB];
        #pragma unroll
        for (int kk = 0; kk < 4; kk++) {
            int k0 = kk * 8;
            unsigned a[4][4];
            #pragma unroll
            for (int mi = 0; mi < 4; mi++)
                ldm_x4(a[mi], aStage + (16 * mi * 36 + k0) * 4u);
            #pragma unroll
            for (int nj = 0; nj < 4; nj++) {
                unsigned bb[2] = { fu(cB[(k0 + t) * 136 + n0 + 8 * nj + g]),
                                   fu(cB[(k0 + t + 4) * 136 + n0 + 8 * nj + g]) };
                #pragma unroll
                for (int mi = 0; mi < 4; mi++) mma_tf32(acc[mi][nj], a[mi], bb);
            }
        }
        sc = (sc == 2) ? 0 : sc + 1;
        sp = (sp == 2) ? 0 : sp + 1;
    }

    #pragma unroll
    for (int mi = 0; mi < 4; mi++) {
        int row = mbase + m0 + 16 * mi + g;
        #pragma unroll
        for (int nj = 0; nj < 4; nj++) {
            int col = nbase + n0 + 8 * nj + 2 * t;
            float2 v0 = make_float2(acc[mi][nj][0] + bf[col],
                                    acc[mi][nj][1] + bf[col + 1]);
            *(float2*)&out[row * PD + col] = v0;
            float2 v1 = make_float2(acc[mi][nj][2] + bf[col],
                                    acc[mi][nj][3] + bf[col + 1]);
            *(float2*)&out[(row + 8) * PD + col] = v1;
        }
    }
}

// =====================================================================
extern "C" void kernel_launch(void* const* d_in, const int* in_sizes, int n_in,
                              void* d_out, int out_size)
{
    const float* X    = (const float*)d_in[0];
    const int*   mask = (const int*)  d_in[1];
    const float* Wq   = (const float*)d_in[2];
    const float* bq   = (const float*)d_in[3];
    const float* Wk   = (const float*)d_in[4];
    const float* bk   = (const float*)d_in[5];
    const float* Wv   = (const float*)d_in[6];
    const float* bv   = (const float*)d_in[7];
    const float* Wf   = (const float*)d_in[8];
    const float* bf   = (const float*)d_in[9];
    float* out = (float*)d_out;

    cudaFuncSetAttribute(attn_kernel,
                         cudaFuncAttributeMaxDynamicSharedMemorySize, ATTN_SMEM);
    cudaFuncSetAttribute(fuse_kernel,
                         cudaFuncAttributeMaxDynamicSharedMemorySize, FUSE_SMEM);

    prep_kernel<<<1024, 256>>>(Wf);
    qkv_kernel<<<dim3(64, 16), 128>>>(X, Wq, bq, Wk, bk, Wv, bv);
    attn_kernel<<<dim3(PT / 64, PBH), 128, ATTN_SMEM>>>(mask);
    fuse_kernel<<<dim3(PD / 128, (PB * PT) / 128), 256, FUSE_SMEM>>>(bf, out);
}